// round 1
// baseline (speedup 1.0000x reference)
#include <cuda_runtime.h>
#include <math.h>

#define D_MODEL 1024
#define D_INNER 2048
#define D_STATE 16
#define DT_RANK 64
#define NB 2
#define TSEQ 2048
#define MROWS (NB*TSEQ)   /* 4096 */
#define EPSV 1e-6f

// ---------------- scratch (no allocations allowed) ----------------
__device__ float g_xn[MROWS * D_MODEL];          // 16 MB
__device__ float g_xz[MROWS * 2 * D_INNER];      // 64 MB
__device__ float g_xconv[MROWS * D_INNER];       // 32 MB
__device__ float g_xdbc[MROWS * 96];             // 1.5 MB
__device__ float g_dc[MROWS * D_INNER];          // 32 MB
__device__ float g_du[MROWS * D_INNER];          // 32 MB
__device__ float g_y[MROWS * D_INNER];           // 32 MB

// ---------------- RMSNorm ----------------
__global__ void rmsnorm_kernel(const float* __restrict__ x,
                               const float* __restrict__ w,
                               float* __restrict__ out) {
    int row = blockIdx.x;
    int tid = threadIdx.x;            // 256 threads, 1024 floats/row -> 1 float4/thread
    const float4* xr = (const float4*)(x + (size_t)row * D_MODEL);
    float4 v = xr[tid];
    float ss = v.x*v.x + v.y*v.y + v.z*v.z + v.w*v.w;
    // warp reduce
    #pragma unroll
    for (int off = 16; off > 0; off >>= 1)
        ss += __shfl_xor_sync(0xffffffffu, ss, off);
    __shared__ float red[8];
    __shared__ float sscale;
    int lane = tid & 31, wq = tid >> 5;
    if (lane == 0) red[wq] = ss;
    __syncthreads();
    if (tid == 0) {
        float t = 0.f;
        #pragma unroll
        for (int i = 0; i < 8; i++) t += red[i];
        sscale = rsqrtf(t * (1.0f / D_MODEL) + EPSV);
    }
    __syncthreads();
    float sc = sscale;
    float4 wv = ((const float4*)w)[tid];
    float4 o;
    o.x = v.x * sc * wv.x; o.y = v.y * sc * wv.y;
    o.z = v.z * sc * wv.z; o.w = v.w * sc * wv.w;
    ((float4*)(out + (size_t)row * D_MODEL))[tid] = o;
}

// ---------------- generic SGEMM:  C(M,N) = A(M,K) * B(N,K)^T  + epilogue ----------------
// EPI 0: plain store
// EPI 1: dt epilogue:  v+=bias(e0[n]); sp=softplus; dc=clip(sp,-10,1); C=dc; o2=dc*e1[m*ldc+n]
// EPI 2: residual add: C = v + e0[m*ldc+n]
template<int EPI>
__global__ __launch_bounds__(256) void sgemm_kernel(
        const float* __restrict__ A, const float* __restrict__ B,
        float* __restrict__ C, int M, int N, int K,
        int lda, int ldb, int ldc,
        const float* __restrict__ e0, const float* __restrict__ e1,
        float* __restrict__ o2)
{
    __shared__ float As[8][128];
    __shared__ float Bs[8][128];
    int tid = threadIdx.x;
    int m0 = blockIdx.y * 128;
    int n0 = blockIdx.x * 128;
    int lrow = tid >> 1;            // 0..127
    int lcol = (tid & 1) * 4;       // 0 or 4
    const float* Aptr = A + (size_t)(m0 + lrow) * lda + lcol;
    const float* Bptr = B + (size_t)(n0 + lrow) * ldb + lcol;
    bool bvalid = (n0 + lrow) < N;
    int tx = tid & 15, ty = tid >> 4;

    float acc[8][8];
    #pragma unroll
    for (int i = 0; i < 8; i++)
        #pragma unroll
        for (int j = 0; j < 8; j++) acc[i][j] = 0.f;

    for (int k0 = 0; k0 < K; k0 += 8) {
        float4 av = *(const float4*)(Aptr + k0);
        float4 bv = bvalid ? *(const float4*)(Bptr + k0) : make_float4(0.f,0.f,0.f,0.f);
        As[lcol+0][lrow] = av.x; As[lcol+1][lrow] = av.y;
        As[lcol+2][lrow] = av.z; As[lcol+3][lrow] = av.w;
        Bs[lcol+0][lrow] = bv.x; Bs[lcol+1][lrow] = bv.y;
        Bs[lcol+2][lrow] = bv.z; Bs[lcol+3][lrow] = bv.w;
        __syncthreads();
        #pragma unroll
        for (int k = 0; k < 8; k++) {
            float4 a0 = *(const float4*)&As[k][ty*8];
            float4 a1 = *(const float4*)&As[k][ty*8+4];
            float4 b0 = *(const float4*)&Bs[k][tx*8];
            float4 b1 = *(const float4*)&Bs[k][tx*8+4];
            float ra[8] = {a0.x,a0.y,a0.z,a0.w,a1.x,a1.y,a1.z,a1.w};
            float rb[8] = {b0.x,b0.y,b0.z,b0.w,b1.x,b1.y,b1.z,b1.w};
            #pragma unroll
            for (int i = 0; i < 8; i++)
                #pragma unroll
                for (int j = 0; j < 8; j++)
                    acc[i][j] = fmaf(ra[i], rb[j], acc[i][j]);
        }
        __syncthreads();
    }

    #pragma unroll
    for (int i = 0; i < 8; i++) {
        int m = m0 + ty*8 + i;
        #pragma unroll
        for (int j = 0; j < 8; j++) {
            int n = n0 + tx*8 + j;
            if (n >= N) continue;
            float v = acc[i][j];
            size_t cidx = (size_t)m * ldc + n;
            if (EPI == 0) {
                C[cidx] = v;
            } else if (EPI == 1) {
                v += e0[n];
                float sp = (v > 20.f) ? v : log1pf(__expf(v));
                float dcv = fminf(fmaxf(sp, -10.f), 1.f);
                C[cidx] = dcv;
                o2[cidx] = dcv * e1[cidx];
            } else {
                C[cidx] = v + e0[cidx];
            }
        }
    }
}

// ---------------- depthwise causal conv(4) + silu ----------------
__global__ void conv_silu_kernel(const float* __restrict__ cw,
                                 const float* __restrict__ cb) {
    int idx = blockIdx.x * 256 + threadIdx.x;      // over MROWS * 512 float4s
    if (idx >= MROWS * (D_INNER/4)) return;
    int d4 = idx & (D_INNER/4 - 1);
    int bt = idx >> 9;                 // row index b*T+t
    int t  = bt & (TSEQ - 1);
    int d  = d4 * 4;
    float wv[4][4];                    // [channel][tap]
    *(float4*)wv[0] = *(const float4*)(cw + (d+0)*4);
    *(float4*)wv[1] = *(const float4*)(cw + (d+1)*4);
    *(float4*)wv[2] = *(const float4*)(cw + (d+2)*4);
    *(float4*)wv[3] = *(const float4*)(cw + (d+3)*4);
    float4 bvv = *(const float4*)(cb + d);
    float a0 = bvv.x, a1 = bvv.y, a2 = bvv.z, a3 = bvv.w;
    #pragma unroll
    for (int k = 0; k < 4; k++) {
        int tt = t - 3 + k;
        if (tt < 0) continue;
        const float4 xv = *(const float4*)(g_xz + (size_t)(bt - t + tt) * (2*D_INNER) + d);
        a0 = fmaf(wv[0][k], xv.x, a0);
        a1 = fmaf(wv[1][k], xv.y, a1);
        a2 = fmaf(wv[2][k], xv.z, a2);
        a3 = fmaf(wv[3][k], xv.w, a3);
    }
    float4 o;
    o.x = a0 / (1.f + __expf(-a0));
    o.y = a1 / (1.f + __expf(-a1));
    o.z = a2 / (1.f + __expf(-a2));
    o.w = a3 / (1.f + __expf(-a3));
    *(float4*)(g_xconv + (size_t)bt * D_INNER + d) = o;
}

// ---------------- x_proj:  x_dbc(M,96) = x_conv(M,2048) @ x_proj_w(96,2048)^T ----------------
// block: 256 thr = 8 warps; 4 rows staged in smem; warp w owns 12 n's.
__global__ __launch_bounds__(256) void xproj_kernel(const float* __restrict__ xconv,
                                                    const float* __restrict__ w,
                                                    float* __restrict__ out) {
    __shared__ float sx[4][D_INNER];   // 32 KB
    int r0 = blockIdx.x * 4;
    const float4* src = (const float4*)(xconv + (size_t)r0 * D_INNER);
    float4* dst = (float4*)sx;
    for (int i = threadIdx.x; i < 4 * (D_INNER/4); i += 256) dst[i] = src[i];
    __syncthreads();
    int wq = threadIdx.x >> 5, lane = threadIdx.x & 31;
    for (int nn = 0; nn < 12; nn++) {
        int n = wq * 12 + nn;          // 0..95
        float acc[4] = {0.f, 0.f, 0.f, 0.f};
        const float4* wrow = (const float4*)(w + (size_t)n * D_INNER);
        #pragma unroll 4
        for (int i = 0; i < 16; i++) {
            float4 wv = wrow[i*32 + lane];
            #pragma unroll
            for (int r = 0; r < 4; r++) {
                float4 xv = *(const float4*)&sx[r][(i*32 + lane)*4];
                acc[r] += wv.x*xv.x + wv.y*xv.y + wv.z*xv.z + wv.w*xv.w;
            }
        }
        #pragma unroll
        for (int r = 0; r < 4; r++) {
            float a = acc[r];
            a += __shfl_xor_sync(0xffffffffu, a, 16);
            a += __shfl_xor_sync(0xffffffffu, a, 8);
            a += __shfl_xor_sync(0xffffffffu, a, 4);
            a += __shfl_xor_sync(0xffffffffu, a, 2);
            a += __shfl_xor_sync(0xffffffffu, a, 1);
            if (lane == 0) out[(size_t)(r0 + r) * 96 + n] = a;
        }
    }
}

// ---------------- selective scan + output epilogue ----------------
// block: 256 thr = 8 warps; warp = 2 channels x 16 states; block = 16 channels, one batch.
// grid = NB * (D_INNER/16) = 256 blocks.
__global__ __launch_bounds__(256) void scan_kernel(const float* __restrict__ A_log,
                                                   const float* __restrict__ Dp) {
    __shared__ float sB[64*16], sC[64*16], sdc[64*16], sdu[64*16];  // 16 KB
    int bid = blockIdx.x;
    int b = bid >> 7;
    int d0 = (bid & 127) << 4;
    int tid = threadIdx.x;
    int w = tid >> 5, lane = tid & 31;
    int s = lane & 15, half = lane >> 4;
    int cl = w * 2 + half;             // channel-local 0..15
    int d = d0 + cl;
    float Aval = -__expf(A_log[d * D_STATE + s]);
    float Dv = Dp[d];
    float h = 0.f;
    for (int t0 = 0; t0 < TSEQ; t0 += 64) {
        __syncthreads();
        for (int i = tid; i < 1024; i += 256) {
            int ti = i >> 4, j = i & 15;
            size_t row = (size_t)b * TSEQ + t0 + ti;
            sB[i]  = g_xdbc[row * 96 + 64 + j];
            sC[i]  = g_xdbc[row * 96 + 80 + j];
            sdc[i] = g_dc[row * D_INNER + d0 + j];
            sdu[i] = g_du[row * D_INNER + d0 + j];
        }
        __syncthreads();
        for (int i = 0; i < 64; i++) {
            float dcv = sdc[i*16 + cl];
            float duv = sdu[i*16 + cl];
            float r = __expf(dcv * Aval);
            h = fmaf(r, h, duv * sB[i*16 + s]);
            float p = h * sC[i*16 + s];
            p += __shfl_xor_sync(0xffffffffu, p, 8);
            p += __shfl_xor_sync(0xffffffffu, p, 4);
            p += __shfl_xor_sync(0xffffffffu, p, 2);
            p += __shfl_xor_sync(0xffffffffu, p, 1);
            if (s == 0) {
                size_t row = (size_t)b * TSEQ + t0 + i;
                float xc = g_xconv[row * D_INNER + d];
                float zv = g_xz[row * (2*D_INNER) + D_INNER + d];
                float sig = 1.f / (1.f + __expf(-zv));
                g_y[row * D_INNER + d] = (p + xc * Dv) * (zv * sig);
            }
        }
    }
}

// ---------------- launch ----------------
extern "C" void kernel_launch(void* const* d_in, const int* in_sizes, int n_in,
                              void* d_out, int out_size) {
    (void)in_sizes; (void)n_in; (void)out_size;
    const float* x          = (const float*)d_in[0];
    const float* in_proj_w  = (const float*)d_in[1];
    const float* conv_w     = (const float*)d_in[2];
    const float* conv_b     = (const float*)d_in[3];
    const float* x_proj_w   = (const float*)d_in[4];
    const float* dt_proj_w  = (const float*)d_in[5];
    const float* dt_proj_b  = (const float*)d_in[6];
    const float* A_log      = (const float*)d_in[7];
    const float* Dp         = (const float*)d_in[8];
    const float* out_proj_w = (const float*)d_in[9];
    const float* norm_w     = (const float*)d_in[10];
    float* out = (float*)d_out;

    float *xn, *xz, *xconv, *xdbc, *dcb, *dub, *yb;
    cudaGetSymbolAddress((void**)&xn,    g_xn);
    cudaGetSymbolAddress((void**)&xz,    g_xz);
    cudaGetSymbolAddress((void**)&xconv, g_xconv);
    cudaGetSymbolAddress((void**)&xdbc,  g_xdbc);
    cudaGetSymbolAddress((void**)&dcb,   g_dc);
    cudaGetSymbolAddress((void**)&dub,   g_du);
    cudaGetSymbolAddress((void**)&yb,    g_y);

    // 1. rmsnorm
    rmsnorm_kernel<<<MROWS, 256>>>(x, norm_w, xn);

    // 2. in_proj: xz(4096,4096) = xn(4096,1024) @ in_proj_w(4096,1024)^T
    sgemm_kernel<0><<<dim3(32, 32), 256>>>(xn, in_proj_w, xz,
        MROWS, 2*D_INNER, D_MODEL, D_MODEL, D_MODEL, 2*D_INNER,
        nullptr, nullptr, nullptr);

    // 3. depthwise conv + silu -> x_conv
    conv_silu_kernel<<<(MROWS * (D_INNER/4) + 255) / 256, 256>>>(conv_w, conv_b);

    // 4. x_proj: x_dbc(4096,96) = x_conv @ x_proj_w^T
    xproj_kernel<<<MROWS / 4, 256>>>(xconv, x_proj_w, xdbc);

    // 5. dt_proj + softplus/clip/du epilogue
    sgemm_kernel<1><<<dim3(16, 32), 256>>>(xdbc, dt_proj_w, dcb,
        MROWS, D_INNER, DT_RANK, 96, DT_RANK, D_INNER,
        dt_proj_b, xconv, dub);

    // 6. selective scan + (y + x_conv*D)*silu(z) epilogue -> g_y
    scan_kernel<<<NB * (D_INNER/16), 256>>>(A_log, Dp);

    // 7. out_proj + residual
    sgemm_kernel<2><<<dim3(8, 32), 256>>>(yb, out_proj_w, out,
        MROWS, D_MODEL, D_INNER, D_INNER, D_INNER, D_MODEL,
        x, nullptr, nullptr);
}

// round 3
// speedup vs baseline: 1.3289x; 1.3289x over previous
#include <cuda_runtime.h>
#include <cuda_bf16.h>
#include <math.h>
#include <stdint.h>

#define D_MODEL 1024
#define D_INNER 2048
#define D_STATE 16
#define DT_RANK 64
#define NB 2
#define TSEQ 2048
#define MROWS (NB*TSEQ)   /* 4096 */
#define EPSV 1e-6f

typedef __nv_bfloat16 bf16;

// ---------------- scratch (no allocations allowed) ----------------
__device__ bf16  g_xnh[MROWS*D_MODEL],  g_xnl[MROWS*D_MODEL];
__device__ bf16  g_inwh[2*D_INNER*D_MODEL], g_inwl[2*D_INNER*D_MODEL];
__device__ bf16  g_xpwh[96*D_INNER],    g_xpwl[96*D_INNER];
__device__ bf16  g_dtwh[D_INNER*DT_RANK], g_dtwl[D_INNER*DT_RANK];
__device__ bf16  g_opwh[D_MODEL*D_INNER], g_opwl[D_MODEL*D_INNER];
__device__ float g_xz[MROWS*2*D_INNER];
__device__ float g_xconv[MROWS*D_INNER];
__device__ bf16  g_xch[MROWS*D_INNER],  g_xcl[MROWS*D_INNER];
__device__ float g_xdbc[MROWS*96];
__device__ bf16  g_dth[MROWS*DT_RANK],  g_dtl[MROWS*DT_RANK];
__device__ float g_dc[MROWS*D_INNER],   g_du[MROWS*D_INNER];
__device__ bf16  g_yh[MROWS*D_INNER],   g_yl[MROWS*D_INNER];

// ---------------- helpers ----------------
__device__ __forceinline__ uint32_t s2u(const void* p) {
    uint32_t a;
    asm("{ .reg .u64 t; cvta.to.shared.u64 t, %1; cvt.u32.u64 %0, t; }" : "=r"(a) : "l"(p));
    return a;
}
__device__ __forceinline__ void cpa16(uint32_t dst, const void* src) {
    asm volatile("cp.async.cg.shared.global [%0], [%1], 16;" :: "r"(dst), "l"(src) : "memory");
}
__device__ __forceinline__ void cpa16z(uint32_t dst, const void* src, int sz) {
    asm volatile("cp.async.cg.shared.global [%0], [%1], 16, %2;" :: "r"(dst), "l"(src), "r"(sz) : "memory");
}
#define CPA_COMMIT() asm volatile("cp.async.commit_group;" ::: "memory")

#define LDSM4(r, a) \
    asm volatile("ldmatrix.sync.aligned.m8n8.x4.shared.b16 {%0,%1,%2,%3}, [%4];" \
        : "=r"((r)[0]),"=r"((r)[1]),"=r"((r)[2]),"=r"((r)[3]) : "r"(a))

#define MMA16816(d, a, b0, b1) \
    asm volatile("mma.sync.aligned.m16n8k16.row.col.f32.bf16.bf16.f32 " \
        "{%0,%1,%2,%3}, {%4,%5,%6,%7}, {%8,%9}, {%0,%1,%2,%3};" \
        : "+f"((d)[0]),"+f"((d)[1]),"+f"((d)[2]),"+f"((d)[3]) \
        : "r"((a)[0]),"r"((a)[1]),"r"((a)[2]),"r"((a)[3]), "r"(b0),"r"(b1))

// ---------------- split-bf16 GEMM via mma.sync ----------------
// C(M,128-tile) = A(M,K) * B(N,K)^T with K' = 3K segments:
//   seg0: Ah*Bh   seg1: Al*Bh   seg2: Ah*Bl
// EPI 0: C=v      EPI 1: dt epi (softplus/clip -> dc, du)
// EPI 2: C=v+res  EPI 4: atomicAdd (split-K)
#define STG_BYTES 20480
#define GEMM_SMEM (4*STG_BYTES)

template<int EPI>
__global__ __launch_bounds__(256, 1)
void gemm_mma(const bf16* __restrict__ Ah, const bf16* __restrict__ Al,
              const bf16* __restrict__ Bh, const bf16* __restrict__ Bl,
              int K, int Nreal, int ldc,
              float* __restrict__ o0, float* __restrict__ o1,
              const float* __restrict__ e0, const float* __restrict__ e1)
{
    extern __shared__ char dyn[];
    const uint32_t sbase = s2u(dyn);
    const int tid = threadIdx.x, lane = tid & 31, wid = tid >> 5;
    const int wm = wid >> 2, wn = wid & 3;           // 2 x 4 warp grid
    const int m0 = blockIdx.y * 128, n0 = blockIdx.x * 128;
    const int NCtot = 3 * K / 32;
    const int per = (NCtot + gridDim.z - 1) / gridDim.z;
    const int kc0 = blockIdx.z * per;
    const int kc1 = min(NCtot, kc0 + per);

    float acc[4][4][4];
    #pragma unroll
    for (int i = 0; i < 4; i++)
        #pragma unroll
        for (int j = 0; j < 4; j++)
            #pragma unroll
            for (int k = 0; k < 4; k++) acc[i][j][k] = 0.f;

    auto load_stage = [&](int s, int kc) {
        int kb = kc * 32;
        int seg = kb / K;
        int kk = kb - seg * K;
        const bf16* Asrc = (seg == 1) ? Al : Ah;
        const bf16* Bsrc = (seg == 2) ? Bl : Bh;
        uint32_t st = sbase + s * STG_BYTES;
        #pragma unroll
        for (int j = 0; j < 2; j++) {
            int idx = tid + j * 256;                 // 512 chunks: 128 rows x 4
            int row = idx >> 2, c = idx & 3;
            cpa16(st + row * 80 + c * 16, Asrc + (size_t)(m0 + row) * K + kk + c * 8);
        }
        #pragma unroll
        for (int j = 0; j < 2; j++) {
            int idx = tid + j * 256;
            int row = idx >> 2, c = idx & 3;
            int nr = n0 + row;
            int ok = nr < Nreal;
            cpa16z(st + 10240 + row * 80 + c * 16,
                   Bsrc + (size_t)(ok ? nr : 0) * K + kk + c * 8, ok ? 16 : 0);
        }
    };

    #pragma unroll
    for (int s = 0; s < 3; s++) {
        if (kc0 + s < kc1) load_stage(s, kc0 + s);
        CPA_COMMIT();
    }

    for (int kc = kc0; kc < kc1; kc++) {
        int i = kc - kc0;
        int s = i & 3;
        asm volatile("cp.async.wait_group 2;" ::: "memory");
        __syncthreads();
        if (kc + 3 < kc1) load_stage((i + 3) & 3, kc + 3);
        CPA_COMMIT();

        uint32_t sA = sbase + s * STG_BYTES;
        uint32_t sB = sA + 10240;
        #pragma unroll
        for (int ks = 0; ks < 2; ks++) {
            uint32_t a[4][4], b[2][4];
            #pragma unroll
            for (int mi = 0; mi < 4; mi++) {
                uint32_t ad = sA + (uint32_t)(wm*64 + mi*16 + (lane & 15)) * 80
                              + ks * 32 + (lane >> 4) * 16;
                LDSM4(a[mi], ad);
            }
            #pragma unroll
            for (int g = 0; g < 2; g++) {
                uint32_t bd = sB + (uint32_t)(wn*32 + g*16 + (lane & 7) + ((lane >> 4) & 1) * 8) * 80
                              + ks * 32 + ((lane >> 3) & 1) * 16;
                LDSM4(b[g], bd);
            }
            #pragma unroll
            for (int mi = 0; mi < 4; mi++)
                #pragma unroll
                for (int nj = 0; nj < 4; nj++) {
                    int bg = nj >> 1, br = (nj & 1) * 2;
                    MMA16816(acc[mi][nj], a[mi], b[bg][br], b[bg][br+1]);
                }
        }
    }

    // ---- epilogue straight from registers ----
    #pragma unroll
    for (int mi = 0; mi < 4; mi++)
        #pragma unroll
        for (int nj = 0; nj < 4; nj++)
            #pragma unroll
            for (int h = 0; h < 2; h++) {
                int m = m0 + wm*64 + mi*16 + (lane >> 2) + h*8;
                int nb = n0 + wn*32 + nj*8 + (lane & 3)*2;
                #pragma unroll
                for (int q = 0; q < 2; q++) {
                    int n = nb + q;
                    float v = acc[mi][nj][h*2 + q];
                    if (EPI == 0) {
                        o0[(size_t)m * ldc + n] = v;
                    } else if (EPI == 1) {
                        v += e0[n];
                        float sp = (v > 20.f) ? v : log1pf(__expf(v));
                        float dcv = fminf(fmaxf(sp, -10.f), 1.f);
                        size_t ci = (size_t)m * ldc + n;
                        o0[ci] = dcv;
                        o1[ci] = dcv * e1[ci];
                    } else if (EPI == 2) {
                        size_t ci = (size_t)m * ldc + n;
                        o0[ci] = v + e0[ci];
                    } else {
                        if (n < Nreal) atomicAdd(o0 + (size_t)m * ldc + n, v);
                    }
                }
            }
}

// ---------------- hi/lo split of a float array ----------------
__global__ void split4_kernel(const float4* __restrict__ src,
                              bf16* __restrict__ hi, bf16* __restrict__ lo, int n4) {
    int i = blockIdx.x * 256 + threadIdx.x;
    if (i >= n4) return;
    float4 v = src[i];
    bf16 h0 = __float2bfloat16(v.x), h1 = __float2bfloat16(v.y);
    bf16 h2 = __float2bfloat16(v.z), h3 = __float2bfloat16(v.w);
    __nv_bfloat162 p0, p1, q0, q1;
    p0.x = h0; p0.y = h1; p1.x = h2; p1.y = h3;
    q0.x = __float2bfloat16(v.x - __bfloat162float(h0));
    q0.y = __float2bfloat16(v.y - __bfloat162float(h1));
    q1.x = __float2bfloat16(v.z - __bfloat162float(h2));
    q1.y = __float2bfloat16(v.w - __bfloat162float(h3));
    *(__nv_bfloat162*)(hi + (size_t)i * 4)     = p0;
    *(__nv_bfloat162*)(hi + (size_t)i * 4 + 2) = p1;
    *(__nv_bfloat162*)(lo + (size_t)i * 4)     = q0;
    *(__nv_bfloat162*)(lo + (size_t)i * 4 + 2) = q1;
}

__global__ void zero_kernel(float* __restrict__ p, int n) {
    int i = blockIdx.x * 256 + threadIdx.x;
    if (i < n) p[i] = 0.f;
}

__global__ void dtsplit_kernel() {
    int i = blockIdx.x * 256 + threadIdx.x;
    if (i >= MROWS * DT_RANK) return;
    int m = i >> 6, n = i & 63;
    float v = g_xdbc[(size_t)m * 96 + n];
    bf16 h = __float2bfloat16(v);
    g_dth[i] = h;
    g_dtl[i] = __float2bfloat16(v - __bfloat162float(h));
}

// ---------------- RMSNorm -> split bf16 ----------------
__global__ void rmsnorm_kernel(const float* __restrict__ x,
                               const float* __restrict__ w,
                               bf16* __restrict__ oh, bf16* __restrict__ ol) {
    int row = blockIdx.x;
    int tid = threadIdx.x;
    const float4* xr = (const float4*)(x + (size_t)row * D_MODEL);
    float4 v = xr[tid];
    float ss = v.x*v.x + v.y*v.y + v.z*v.z + v.w*v.w;
    #pragma unroll
    for (int off = 16; off > 0; off >>= 1)
        ss += __shfl_xor_sync(0xffffffffu, ss, off);
    __shared__ float red[8];
    __shared__ float sscale;
    int lane = tid & 31, wq = tid >> 5;
    if (lane == 0) red[wq] = ss;
    __syncthreads();
    if (tid == 0) {
        float t = 0.f;
        #pragma unroll
        for (int i = 0; i < 8; i++) t += red[i];
        sscale = rsqrtf(t * (1.0f / D_MODEL) + EPSV);
    }
    __syncthreads();
    float sc = sscale;
    float4 wv = ((const float4*)w)[tid];
    float o0 = v.x*sc*wv.x, o1 = v.y*sc*wv.y, o2 = v.z*sc*wv.z, o3 = v.w*sc*wv.w;
    size_t base = (size_t)row * D_MODEL + tid * 4;
    bf16 h0=__float2bfloat16(o0), h1=__float2bfloat16(o1), h2=__float2bfloat16(o2), h3=__float2bfloat16(o3);
    __nv_bfloat162 ph0, ph1, pl0, pl1;
    ph0.x=h0; ph0.y=h1; ph1.x=h2; ph1.y=h3;
    pl0.x=__float2bfloat16(o0-__bfloat162float(h0));
    pl0.y=__float2bfloat16(o1-__bfloat162float(h1));
    pl1.x=__float2bfloat16(o2-__bfloat162float(h2));
    pl1.y=__float2bfloat16(o3-__bfloat162float(h3));
    *(__nv_bfloat162*)(oh+base)   = ph0; *(__nv_bfloat162*)(oh+base+2) = ph1;
    *(__nv_bfloat162*)(ol+base)   = pl0; *(__nv_bfloat162*)(ol+base+2) = pl1;
}

// ---------------- depthwise causal conv(4) + silu (+bf16 split) ----------------
__global__ void conv_silu_kernel(const float* __restrict__ cw,
                                 const float* __restrict__ cb) {
    int idx = blockIdx.x * 256 + threadIdx.x;
    if (idx >= MROWS * (D_INNER/4)) return;
    int d4 = idx & (D_INNER/4 - 1);
    int bt = idx >> 9;
    int t  = bt & (TSEQ - 1);
    int d  = d4 * 4;
    float wv[4][4];
    *(float4*)wv[0] = *(const float4*)(cw + (d+0)*4);
    *(float4*)wv[1] = *(const float4*)(cw + (d+1)*4);
    *(float4*)wv[2] = *(const float4*)(cw + (d+2)*4);
    *(float4*)wv[3] = *(const float4*)(cw + (d+3)*4);
    float4 bvv = *(const float4*)(cb + d);
    float a0 = bvv.x, a1 = bvv.y, a2 = bvv.z, a3 = bvv.w;
    #pragma unroll
    for (int k = 0; k < 4; k++) {
        int tt = t - 3 + k;
        if (tt < 0) continue;
        const float4 xv = *(const float4*)(g_xz + (size_t)(bt - t + tt) * (2*D_INNER) + d);
        a0 = fmaf(wv[0][k], xv.x, a0);
        a1 = fmaf(wv[1][k], xv.y, a1);
        a2 = fmaf(wv[2][k], xv.z, a2);
        a3 = fmaf(wv[3][k], xv.w, a3);
    }
    float o0 = a0/(1.f+__expf(-a0)), o1 = a1/(1.f+__expf(-a1));
    float o2 = a2/(1.f+__expf(-a2)), o3 = a3/(1.f+__expf(-a3));
    size_t base = (size_t)bt * D_INNER + d;
    *(float4*)(g_xconv + base) = make_float4(o0,o1,o2,o3);
    bf16 h0=__float2bfloat16(o0), h1=__float2bfloat16(o1), h2=__float2bfloat16(o2), h3=__float2bfloat16(o3);
    __nv_bfloat162 ph0, ph1, pl0, pl1;
    ph0.x=h0; ph0.y=h1; ph1.x=h2; ph1.y=h3;
    pl0.x=__float2bfloat16(o0-__bfloat162float(h0));
    pl0.y=__float2bfloat16(o1-__bfloat162float(h1));
    pl1.x=__float2bfloat16(o2-__bfloat162float(h2));
    pl1.y=__float2bfloat16(o3-__bfloat162float(h3));
    *(__nv_bfloat162*)(g_xch+base)   = ph0; *(__nv_bfloat162*)(g_xch+base+2) = ph1;
    *(__nv_bfloat162*)(g_xcl+base)   = pl0; *(__nv_bfloat162*)(g_xcl+base+2) = pl1;
}

// ---------------- selective scan + output epilogue ----------------
__global__ __launch_bounds__(256) void scan_kernel(const float* __restrict__ A_log,
                                                   const float* __restrict__ Dp) {
    __shared__ float sB[64*16], sC[64*16], sdc[64*16], sdu[64*16];
    int bid = blockIdx.x;
    int b = bid >> 7;
    int d0 = (bid & 127) << 4;
    int tid = threadIdx.x;
    int w = tid >> 5, lane = tid & 31;
    int s = lane & 15, half = lane >> 4;
    int cl = w * 2 + half;
    int d = d0 + cl;
    float Aval = -__expf(A_log[d * D_STATE + s]);
    float Dv = Dp[d];
    float h = 0.f;
    for (int t0 = 0; t0 < TSEQ; t0 += 64) {
        __syncthreads();
        for (int i = tid; i < 1024; i += 256) {
            int ti = i >> 4, j = i & 15;
            size_t row = (size_t)b * TSEQ + t0 + ti;
            sB[i]  = g_xdbc[row * 96 + 64 + j];
            sC[i]  = g_xdbc[row * 96 + 80 + j];
            sdc[i] = g_dc[row * D_INNER + d0 + j];
            sdu[i] = g_du[row * D_INNER + d0 + j];
        }
        __syncthreads();
        for (int i = 0; i < 64; i++) {
            float dcv = sdc[i*16 + cl];
            float duv = sdu[i*16 + cl];
            float r = __expf(dcv * Aval);
            h = fmaf(r, h, duv * sB[i*16 + s]);
            float p = h * sC[i*16 + s];
            p += __shfl_xor_sync(0xffffffffu, p, 8);
            p += __shfl_xor_sync(0xffffffffu, p, 4);
            p += __shfl_xor_sync(0xffffffffu, p, 2);
            p += __shfl_xor_sync(0xffffffffu, p, 1);
            if (s == 0) {
                size_t row = (size_t)b * TSEQ + t0 + i;
                float xc = g_xconv[row * D_INNER + d];
                float zv = g_xz[row * (2*D_INNER) + D_INNER + d];
                float sig = 1.f / (1.f + __expf(-zv));
                float yv = (p + xc * Dv) * (zv * sig);
                bf16 hh = __float2bfloat16(yv);
                g_yh[row * D_INNER + d] = hh;
                g_yl[row * D_INNER + d] = __float2bfloat16(yv - __bfloat162float(hh));
            }
        }
    }
}

// ---------------- launch ----------------
extern "C" void kernel_launch(void* const* d_in, const int* in_sizes, int n_in,
                              void* d_out, int out_size) {
    (void)in_sizes; (void)n_in; (void)out_size;
    const float* x          = (const float*)d_in[0];
    const float* in_proj_w  = (const float*)d_in[1];
    const float* conv_w     = (const float*)d_in[2];
    const float* conv_b     = (const float*)d_in[3];
    const float* x_proj_w   = (const float*)d_in[4];
    const float* dt_proj_w  = (const float*)d_in[5];
    const float* dt_proj_b  = (const float*)d_in[6];
    const float* A_log      = (const float*)d_in[7];
    const float* Dp         = (const float*)d_in[8];
    const float* out_proj_w = (const float*)d_in[9];
    const float* norm_w     = (const float*)d_in[10];
    float* out = (float*)d_out;

    bf16 *xnh, *xnl, *inwh, *inwl, *xpwh, *xpwl, *dtwh, *dtwl, *opwh, *opwl;
    bf16 *xch, *xcl, *dth, *dtl, *yh, *yl;
    float *xz, *xconv, *xdbc, *dcb, *dub;
    cudaGetSymbolAddress((void**)&xnh,  g_xnh);  cudaGetSymbolAddress((void**)&xnl,  g_xnl);
    cudaGetSymbolAddress((void**)&inwh, g_inwh); cudaGetSymbolAddress((void**)&inwl, g_inwl);
    cudaGetSymbolAddress((void**)&xpwh, g_xpwh); cudaGetSymbolAddress((void**)&xpwl, g_xpwl);
    cudaGetSymbolAddress((void**)&dtwh, g_dtwh); cudaGetSymbolAddress((void**)&dtwl, g_dtwl);
    cudaGetSymbolAddress((void**)&opwh, g_opwh); cudaGetSymbolAddress((void**)&opwl, g_opwl);
    cudaGetSymbolAddress((void**)&xch,  g_xch);  cudaGetSymbolAddress((void**)&xcl,  g_xcl);
    cudaGetSymbolAddress((void**)&dth,  g_dth);  cudaGetSymbolAddress((void**)&dtl,  g_dtl);
    cudaGetSymbolAddress((void**)&yh,   g_yh);   cudaGetSymbolAddress((void**)&yl,   g_yl);
    cudaGetSymbolAddress((void**)&xz,    g_xz);
    cudaGetSymbolAddress((void**)&xconv, g_xconv);
    cudaGetSymbolAddress((void**)&xdbc,  g_xdbc);
    cudaGetSymbolAddress((void**)&dcb,   g_dc);
    cudaGetSymbolAddress((void**)&dub,   g_du);

    cudaFuncSetAttribute(gemm_mma<0>, cudaFuncAttributeMaxDynamicSharedMemorySize, GEMM_SMEM);
    cudaFuncSetAttribute(gemm_mma<1>, cudaFuncAttributeMaxDynamicSharedMemorySize, GEMM_SMEM);
    cudaFuncSetAttribute(gemm_mma<2>, cudaFuncAttributeMaxDynamicSharedMemorySize, GEMM_SMEM);
    cudaFuncSetAttribute(gemm_mma<4>, cudaFuncAttributeMaxDynamicSharedMemorySize, GEMM_SMEM);

    // weight hi/lo splits + xdbc zero (independent)
    split4_kernel<<<(2*D_INNER*D_MODEL/4 + 255)/256, 256>>>((const float4*)in_proj_w,  inwh, inwl, 2*D_INNER*D_MODEL/4);
    split4_kernel<<<(96*D_INNER/4 + 255)/256, 256>>>((const float4*)x_proj_w,   xpwh, xpwl, 96*D_INNER/4);
    split4_kernel<<<(D_INNER*DT_RANK/4 + 255)/256, 256>>>((const float4*)dt_proj_w,  dtwh, dtwl, D_INNER*DT_RANK/4);
    split4_kernel<<<(D_MODEL*D_INNER/4 + 255)/256, 256>>>((const float4*)out_proj_w, opwh, opwl, D_MODEL*D_INNER/4);
    zero_kernel<<<(MROWS*96 + 255)/256, 256>>>(xdbc, MROWS*96);

    // 1. rmsnorm (+split)
    rmsnorm_kernel<<<MROWS, 256>>>(x, norm_w, xnh, xnl);

    // 2. in_proj: xz(4096,4096) = xn @ in_proj_w^T
    gemm_mma<0><<<dim3(32, 32, 1), 256, GEMM_SMEM>>>(xnh, xnl, inwh, inwl,
        D_MODEL, 2*D_INNER, 2*D_INNER, xz, nullptr, nullptr, nullptr);

    // 3. conv + silu (+split)
    conv_silu_kernel<<<(MROWS * (D_INNER/4) + 255)/256, 256>>>(conv_w, conv_b);

    // 4. x_proj (split-K=4, atomic accumulate into zeroed xdbc)
    gemm_mma<4><<<dim3(1, 32, 4), 256, GEMM_SMEM>>>(xch, xcl, xpwh, xpwl,
        D_INNER, 96, 96, xdbc, nullptr, nullptr, nullptr);

    // 4b. dt hi/lo split from xdbc[:, :64]
    dtsplit_kernel<<<(MROWS*DT_RANK + 255)/256, 256>>>();

    // 5. dt_proj + softplus/clip/du epilogue
    gemm_mma<1><<<dim3(16, 32, 1), 256, GEMM_SMEM>>>(dth, dtl, dtwh, dtwl,
        DT_RANK, D_INNER, D_INNER, dcb, dub, dt_proj_b, xconv);

    // 6. selective scan + (y + x_conv*D)*silu(z) (+split)
    scan_kernel<<<NB * (D_INNER/16), 256>>>(A_log, Dp);

    // 7. out_proj + residual
    gemm_mma<2><<<dim3(8, 32, 1), 256, GEMM_SMEM>>>(yh, yl, opwh, opwl,
        D_INNER, D_MODEL, D_MODEL, out, nullptr, x, nullptr);
}

// round 4
// speedup vs baseline: 1.4968x; 1.1264x over previous
#include <cuda_runtime.h>
#include <cuda_bf16.h>
#include <math.h>
#include <stdint.h>

#define D_MODEL 1024
#define D_INNER 2048
#define D_STATE 16
#define DT_RANK 64
#define NB 2
#define TSEQ 2048
#define MROWS (NB*TSEQ)   /* 4096 */
#define EPSV 1e-6f

typedef __nv_bfloat16 bf16;

// ---------------- scratch (no allocations allowed) ----------------
__device__ bf16  g_xnh[MROWS*D_MODEL],  g_xnl[MROWS*D_MODEL];
__device__ bf16  g_inwh[2*D_INNER*D_MODEL], g_inwl[2*D_INNER*D_MODEL];
__device__ bf16  g_xpwh[96*D_INNER],    g_xpwl[96*D_INNER];
__device__ bf16  g_dtwh[D_INNER*DT_RANK], g_dtwl[D_INNER*DT_RANK];
__device__ bf16  g_opwh[D_MODEL*D_INNER], g_opwl[D_MODEL*D_INNER];
__device__ float g_xz[MROWS*2*D_INNER];
__device__ float g_xconv[MROWS*D_INNER];
__device__ bf16  g_xch[MROWS*D_INNER],  g_xcl[MROWS*D_INNER];
__device__ float g_xdbc[MROWS*96];
__device__ bf16  g_dth[MROWS*DT_RANK],  g_dtl[MROWS*DT_RANK];
__device__ float g_dc[MROWS*D_INNER],   g_du[MROWS*D_INNER];
__device__ bf16  g_yh[MROWS*D_INNER],   g_yl[MROWS*D_INNER];

// ---------------- helpers ----------------
__device__ __forceinline__ uint32_t s2u(const void* p) {
    uint32_t a;
    asm("{ .reg .u64 t; cvta.to.shared.u64 t, %1; cvt.u32.u64 %0, t; }" : "=r"(a) : "l"(p));
    return a;
}
__device__ __forceinline__ void cpa16(uint32_t dst, const void* src) {
    asm volatile("cp.async.cg.shared.global [%0], [%1], 16;" :: "r"(dst), "l"(src) : "memory");
}
__device__ __forceinline__ void cpa16z(uint32_t dst, const void* src, int sz) {
    asm volatile("cp.async.cg.shared.global [%0], [%1], 16, %2;" :: "r"(dst), "l"(src), "r"(sz) : "memory");
}
#define CPA_COMMIT() asm volatile("cp.async.commit_group;" ::: "memory")

#define LDSM4(r, a) \
    asm volatile("ldmatrix.sync.aligned.m8n8.x4.shared.b16 {%0,%1,%2,%3}, [%4];" \
        : "=r"((r)[0]),"=r"((r)[1]),"=r"((r)[2]),"=r"((r)[3]) : "r"(a))

#define MMA16816(d, a, b0, b1) \
    asm volatile("mma.sync.aligned.m16n8k16.row.col.f32.bf16.bf16.f32 " \
        "{%0,%1,%2,%3}, {%4,%5,%6,%7}, {%8,%9}, {%0,%1,%2,%3};" \
        : "+f"((d)[0]),"+f"((d)[1]),"+f"((d)[2]),"+f"((d)[3]) \
        : "r"((a)[0]),"r"((a)[1]),"r"((a)[2]),"r"((a)[3]), "r"(b0),"r"(b1))

// ---------------- split-bf16 GEMM via mma.sync ----------------
// C = A(M,K) * B(N,K)^T with K' = 3K segments: Ah*Bh, Al*Bh, Ah*Bl
// Tile: 128 x BN, BK=64 (128B rows, SW128 swizzle -> conflict-free ldmatrix)
// 512 threads = 16 warps (4x4), warp tile 32 x (BN/4).
// EPI 0: C=v   EPI 1: dt epi   EPI 2: C=v+res   EPI 4: atomicAdd (split-K)
template<int EPI, int BN>
__global__ __launch_bounds__(512, 1)
void gemm_mma(const bf16* __restrict__ Ah, const bf16* __restrict__ Al,
              const bf16* __restrict__ Bh, const bf16* __restrict__ Bl,
              int K, int Nreal, int ldc,
              float* __restrict__ o0, float* __restrict__ o1,
              const float* __restrict__ e0, const float* __restrict__ e1)
{
    constexpr int STAGE = (128 + BN) * 128;   // bytes per stage
    constexpr int WN = BN / 4;                // warp n-width (64 or 32)
    constexpr int NJ = WN / 8;                // n8 groups per warp (8 or 4)
    constexpr int BG = WN / 16;               // b ldsm groups (4 or 2)
    extern __shared__ char dyn[];
    const uint32_t sbase = s2u(dyn);
    const int tid = threadIdx.x, lane = tid & 31, wid = tid >> 5;
    const int wm = wid >> 2, wn = wid & 3;    // 4 x 4 warp grid
    const int m0 = blockIdx.y * 128, n0 = blockIdx.x * BN;
    const int NCtot = 3 * K / 64;
    const int per = (NCtot + gridDim.z - 1) / gridDim.z;
    const int kc0 = blockIdx.z * per;
    const int kc1 = min(NCtot, kc0 + per);

    float acc[2][NJ][4];
    #pragma unroll
    for (int i = 0; i < 2; i++)
        #pragma unroll
        for (int j = 0; j < NJ; j++)
            #pragma unroll
            for (int k = 0; k < 4; k++) acc[i][j][k] = 0.f;

    auto load_stage = [&](int s, int kc) {
        int kb = kc * 64;
        int seg = kb / K;
        int kk = kb - seg * K;
        const bf16* Asrc = (seg == 1) ? Al : Ah;
        const bf16* Bsrc = (seg == 2) ? Bl : Bh;
        uint32_t st = sbase + s * STAGE;
        #pragma unroll
        for (int j = 0; j < 2; j++) {                 // A: 1024 16B chunks
            int idx = tid + j * 512;
            int r = idx >> 3, c = idx & 7;
            cpa16(st + r * 128 + ((c ^ (r & 7)) * 16),
                  Asrc + (size_t)(m0 + r) * K + kk + c * 8);
        }
        uint32_t sb = st + 128 * 128;
        #pragma unroll
        for (int j = 0; j < BN / 64; j++) {           // B: BN*8 chunks
            int idx = tid + j * 512;
            int r = idx >> 3, c = idx & 7;
            int nr = n0 + r;
            int ok = nr < Nreal;
            cpa16z(sb + r * 128 + ((c ^ (r & 7)) * 16),
                   Bsrc + (size_t)(ok ? nr : 0) * K + kk + c * 8, ok ? 16 : 0);
        }
    };

    #pragma unroll
    for (int s = 0; s < 3; s++) {
        if (kc0 + s < kc1) load_stage(s, kc0 + s);
        CPA_COMMIT();
    }

    for (int kc = kc0; kc < kc1; kc++) {
        int i = kc - kc0;
        int s = i & 3;
        asm volatile("cp.async.wait_group 2;" ::: "memory");
        __syncthreads();
        if (kc + 3 < kc1) load_stage((i + 3) & 3, kc + 3);
        CPA_COMMIT();

        uint32_t sA = sbase + s * STAGE;
        uint32_t sB = sA + 128 * 128;
        #pragma unroll
        for (int ks = 0; ks < 4; ks++) {
            uint32_t a[2][4], b[BG][4];
            #pragma unroll
            for (int mi = 0; mi < 2; mi++) {
                int r = wm * 32 + mi * 16 + (lane & 15);
                int c = (2 * ks + (lane >> 4)) ^ (r & 7);
                LDSM4(a[mi], sA + r * 128 + c * 16);
            }
            #pragma unroll
            for (int g = 0; g < BG; g++) {
                int r = wn * WN + g * 16 + (lane & 7) + ((lane >> 4) & 1) * 8;
                int c = (2 * ks + ((lane >> 3) & 1)) ^ (r & 7);
                LDSM4(b[g], sB + r * 128 + c * 16);
            }
            #pragma unroll
            for (int mi = 0; mi < 2; mi++)
                #pragma unroll
                for (int nj = 0; nj < NJ; nj++) {
                    int bg = nj >> 1, br = (nj & 1) * 2;
                    MMA16816(acc[mi][nj], a[mi], b[bg][br], b[bg][br+1]);
                }
        }
    }

    // ---- epilogue straight from registers (float2 pairs) ----
    #pragma unroll
    for (int mi = 0; mi < 2; mi++)
        #pragma unroll
        for (int nj = 0; nj < NJ; nj++)
            #pragma unroll
            for (int h = 0; h < 2; h++) {
                int m = m0 + wm*32 + mi*16 + (lane >> 2) + h*8;
                int nb = n0 + wn*WN + nj*8 + (lane & 3)*2;
                float vx = acc[mi][nj][h*2], vy = acc[mi][nj][h*2+1];
                size_t ci = (size_t)m * ldc + nb;
                if (EPI == 0) {
                    *(float2*)(o0 + ci) = make_float2(vx, vy);
                } else if (EPI == 1) {
                    vx += e0[nb]; vy += e0[nb+1];
                    float spx = (vx > 20.f) ? vx : log1pf(__expf(vx));
                    float spy = (vy > 20.f) ? vy : log1pf(__expf(vy));
                    float dx = fminf(fmaxf(spx, -10.f), 1.f);
                    float dy = fminf(fmaxf(spy, -10.f), 1.f);
                    float2 ev = *(const float2*)(e1 + ci);
                    *(float2*)(o0 + ci) = make_float2(dx, dy);
                    *(float2*)(o1 + ci) = make_float2(dx * ev.x, dy * ev.y);
                } else if (EPI == 2) {
                    float2 rv = *(const float2*)(e0 + ci);
                    *(float2*)(o0 + ci) = make_float2(vx + rv.x, vy + rv.y);
                } else {
                    if (nb < Nreal) {
                        atomicAdd(o0 + ci, vx);
                        atomicAdd(o0 + ci + 1, vy);
                    }
                }
            }
}

// ---------------- hi/lo split of a float array ----------------
__global__ void split4_kernel(const float4* __restrict__ src,
                              bf16* __restrict__ hi, bf16* __restrict__ lo, int n4) {
    int i = blockIdx.x * 256 + threadIdx.x;
    if (i >= n4) return;
    float4 v = src[i];
    bf16 h0 = __float2bfloat16(v.x), h1 = __float2bfloat16(v.y);
    bf16 h2 = __float2bfloat16(v.z), h3 = __float2bfloat16(v.w);
    __nv_bfloat162 p0, p1, q0, q1;
    p0.x = h0; p0.y = h1; p1.x = h2; p1.y = h3;
    q0.x = __float2bfloat16(v.x - __bfloat162float(h0));
    q0.y = __float2bfloat16(v.y - __bfloat162float(h1));
    q1.x = __float2bfloat16(v.z - __bfloat162float(h2));
    q1.y = __float2bfloat16(v.w - __bfloat162float(h3));
    *(__nv_bfloat162*)(hi + (size_t)i * 4)     = p0;
    *(__nv_bfloat162*)(hi + (size_t)i * 4 + 2) = p1;
    *(__nv_bfloat162*)(lo + (size_t)i * 4)     = q0;
    *(__nv_bfloat162*)(lo + (size_t)i * 4 + 2) = q1;
}

__global__ void zero_kernel(float* __restrict__ p, int n) {
    int i = blockIdx.x * 256 + threadIdx.x;
    if (i < n) p[i] = 0.f;
}

__global__ void dtsplit_kernel() {
    int i = blockIdx.x * 256 + threadIdx.x;
    if (i >= MROWS * DT_RANK) return;
    int m = i >> 6, n = i & 63;
    float v = g_xdbc[(size_t)m * 96 + n];
    bf16 h = __float2bfloat16(v);
    g_dth[i] = h;
    g_dtl[i] = __float2bfloat16(v - __bfloat162float(h));
}

// ---------------- RMSNorm -> split bf16 ----------------
__global__ void rmsnorm_kernel(const float* __restrict__ x,
                               const float* __restrict__ w,
                               bf16* __restrict__ oh, bf16* __restrict__ ol) {
    int row = blockIdx.x;
    int tid = threadIdx.x;
    const float4* xr = (const float4*)(x + (size_t)row * D_MODEL);
    float4 v = xr[tid];
    float ss = v.x*v.x + v.y*v.y + v.z*v.z + v.w*v.w;
    #pragma unroll
    for (int off = 16; off > 0; off >>= 1)
        ss += __shfl_xor_sync(0xffffffffu, ss, off);
    __shared__ float red[8];
    __shared__ float sscale;
    int lane = tid & 31, wq = tid >> 5;
    if (lane == 0) red[wq] = ss;
    __syncthreads();
    if (tid == 0) {
        float t = 0.f;
        #pragma unroll
        for (int i = 0; i < 8; i++) t += red[i];
        sscale = rsqrtf(t * (1.0f / D_MODEL) + EPSV);
    }
    __syncthreads();
    float sc = sscale;
    float4 wv = ((const float4*)w)[tid];
    float o0 = v.x*sc*wv.x, o1 = v.y*sc*wv.y, o2 = v.z*sc*wv.z, o3 = v.w*sc*wv.w;
    size_t base = (size_t)row * D_MODEL + tid * 4;
    bf16 h0=__float2bfloat16(o0), h1=__float2bfloat16(o1), h2=__float2bfloat16(o2), h3=__float2bfloat16(o3);
    __nv_bfloat162 ph0, ph1, pl0, pl1;
    ph0.x=h0; ph0.y=h1; ph1.x=h2; ph1.y=h3;
    pl0.x=__float2bfloat16(o0-__bfloat162float(h0));
    pl0.y=__float2bfloat16(o1-__bfloat162float(h1));
    pl1.x=__float2bfloat16(o2-__bfloat162float(h2));
    pl1.y=__float2bfloat16(o3-__bfloat162float(h3));
    *(__nv_bfloat162*)(oh+base)   = ph0; *(__nv_bfloat162*)(oh+base+2) = ph1;
    *(__nv_bfloat162*)(ol+base)   = pl0; *(__nv_bfloat162*)(ol+base+2) = pl1;
}

// ---------------- depthwise causal conv(4) + silu (+bf16 split) ----------------
__global__ void conv_silu_kernel(const float* __restrict__ cw,
                                 const float* __restrict__ cb) {
    int idx = blockIdx.x * 256 + threadIdx.x;
    if (idx >= MROWS * (D_INNER/4)) return;
    int d4 = idx & (D_INNER/4 - 1);
    int bt = idx >> 9;
    int t  = bt & (TSEQ - 1);
    int d  = d4 * 4;
    float wv[4][4];
    *(float4*)wv[0] = *(const float4*)(cw + (d+0)*4);
    *(float4*)wv[1] = *(const float4*)(cw + (d+1)*4);
    *(float4*)wv[2] = *(const float4*)(cw + (d+2)*4);
    *(float4*)wv[3] = *(const float4*)(cw + (d+3)*4);
    float4 bvv = *(const float4*)(cb + d);
    float a0 = bvv.x, a1 = bvv.y, a2 = bvv.z, a3 = bvv.w;
    #pragma unroll
    for (int k = 0; k < 4; k++) {
        int tt = t - 3 + k;
        if (tt < 0) continue;
        const float4 xv = *(const float4*)(g_xz + (size_t)(bt - t + tt) * (2*D_INNER) + d);
        a0 = fmaf(wv[0][k], xv.x, a0);
        a1 = fmaf(wv[1][k], xv.y, a1);
        a2 = fmaf(wv[2][k], xv.z, a2);
        a3 = fmaf(wv[3][k], xv.w, a3);
    }
    float o0 = a0/(1.f+__expf(-a0)), o1 = a1/(1.f+__expf(-a1));
    float o2 = a2/(1.f+__expf(-a2)), o3 = a3/(1.f+__expf(-a3));
    size_t base = (size_t)bt * D_INNER + d;
    *(float4*)(g_xconv + base) = make_float4(o0,o1,o2,o3);
    bf16 h0=__float2bfloat16(o0), h1=__float2bfloat16(o1), h2=__float2bfloat16(o2), h3=__float2bfloat16(o3);
    __nv_bfloat162 ph0, ph1, pl0, pl1;
    ph0.x=h0; ph0.y=h1; ph1.x=h2; ph1.y=h3;
    pl0.x=__float2bfloat16(o0-__bfloat162float(h0));
    pl0.y=__float2bfloat16(o1-__bfloat162float(h1));
    pl1.x=__float2bfloat16(o2-__bfloat162float(h2));
    pl1.y=__float2bfloat16(o3-__bfloat162float(h3));
    *(__nv_bfloat162*)(g_xch+base)   = ph0; *(__nv_bfloat162*)(g_xch+base+2) = ph1;
    *(__nv_bfloat162*)(g_xcl+base)   = pl0; *(__nv_bfloat162*)(g_xcl+base+2) = pl1;
}

// ---------------- selective scan + output epilogue ----------------
__global__ __launch_bounds__(256) void scan_kernel(const float* __restrict__ A_log,
                                                   const float* __restrict__ Dp) {
    __shared__ float sB[64*16], sC[64*16], sdc[64*16], sdu[64*16];
    int bid = blockIdx.x;
    int b = bid >> 7;
    int d0 = (bid & 127) << 4;
    int tid = threadIdx.x;
    int w = tid >> 5, lane = tid & 31;
    int s = lane & 15, half = lane >> 4;
    int cl = w * 2 + half;
    int d = d0 + cl;
    float Aval = -__expf(A_log[d * D_STATE + s]);
    float Dv = Dp[d];
    float h = 0.f;
    for (int t0 = 0; t0 < TSEQ; t0 += 64) {
        __syncthreads();
        for (int i = tid; i < 1024; i += 256) {
            int ti = i >> 4, j = i & 15;
            size_t row = (size_t)b * TSEQ + t0 + ti;
            sB[i]  = g_xdbc[row * 96 + 64 + j];
            sC[i]  = g_xdbc[row * 96 + 80 + j];
            sdc[i] = g_dc[row * D_INNER + d0 + j];
            sdu[i] = g_du[row * D_INNER + d0 + j];
        }
        __syncthreads();
        for (int i = 0; i < 64; i++) {
            float dcv = sdc[i*16 + cl];
            float duv = sdu[i*16 + cl];
            float r = __expf(dcv * Aval);
            h = fmaf(r, h, duv * sB[i*16 + s]);
            float p = h * sC[i*16 + s];
            p += __shfl_xor_sync(0xffffffffu, p, 8);
            p += __shfl_xor_sync(0xffffffffu, p, 4);
            p += __shfl_xor_sync(0xffffffffu, p, 2);
            p += __shfl_xor_sync(0xffffffffu, p, 1);
            if (s == 0) {
                size_t row = (size_t)b * TSEQ + t0 + i;
                float xc = g_xconv[row * D_INNER + d];
                float zv = g_xz[row * (2*D_INNER) + D_INNER + d];
                float sig = 1.f / (1.f + __expf(-zv));
                float yv = (p + xc * Dv) * (zv * sig);
                bf16 hh = __float2bfloat16(yv);
                g_yh[row * D_INNER + d] = hh;
                g_yl[row * D_INNER + d] = __float2bfloat16(yv - __bfloat162float(hh));
            }
        }
    }
}

// ---------------- launch ----------------
#define SM256 ((128 + 256) * 128 * 4)   /* 196608 */
#define SM128 ((128 + 128) * 128 * 4)   /* 131072 */

extern "C" void kernel_launch(void* const* d_in, const int* in_sizes, int n_in,
                              void* d_out, int out_size) {
    (void)in_sizes; (void)n_in; (void)out_size;
    const float* x          = (const float*)d_in[0];
    const float* in_proj_w  = (const float*)d_in[1];
    const float* conv_w     = (const float*)d_in[2];
    const float* conv_b     = (const float*)d_in[3];
    const float* x_proj_w   = (const float*)d_in[4];
    const float* dt_proj_w  = (const float*)d_in[5];
    const float* dt_proj_b  = (const float*)d_in[6];
    const float* A_log      = (const float*)d_in[7];
    const float* Dp         = (const float*)d_in[8];
    const float* out_proj_w = (const float*)d_in[9];
    const float* norm_w     = (const float*)d_in[10];
    float* out = (float*)d_out;

    bf16 *xnh, *xnl, *inwh, *inwl, *xpwh, *xpwl, *dtwh, *dtwl, *opwh, *opwl;
    bf16 *xch, *xcl, *dth, *dtl, *yh, *yl;
    float *xz, *xconv, *xdbc, *dcb, *dub;
    cudaGetSymbolAddress((void**)&xnh,  g_xnh);  cudaGetSymbolAddress((void**)&xnl,  g_xnl);
    cudaGetSymbolAddress((void**)&inwh, g_inwh); cudaGetSymbolAddress((void**)&inwl, g_inwl);
    cudaGetSymbolAddress((void**)&xpwh, g_xpwh); cudaGetSymbolAddress((void**)&xpwl, g_xpwl);
    cudaGetSymbolAddress((void**)&dtwh, g_dtwh); cudaGetSymbolAddress((void**)&dtwl, g_dtwl);
    cudaGetSymbolAddress((void**)&opwh, g_opwh); cudaGetSymbolAddress((void**)&opwl, g_opwl);
    cudaGetSymbolAddress((void**)&xch,  g_xch);  cudaGetSymbolAddress((void**)&xcl,  g_xcl);
    cudaGetSymbolAddress((void**)&dth,  g_dth);  cudaGetSymbolAddress((void**)&dtl,  g_dtl);
    cudaGetSymbolAddress((void**)&yh,   g_yh);   cudaGetSymbolAddress((void**)&yl,   g_yl);
    cudaGetSymbolAddress((void**)&xz,    g_xz);
    cudaGetSymbolAddress((void**)&xconv, g_xconv);
    cudaGetSymbolAddress((void**)&xdbc,  g_xdbc);
    cudaGetSymbolAddress((void**)&dcb,   g_dc);
    cudaGetSymbolAddress((void**)&dub,   g_du);

    cudaFuncSetAttribute((const void*)gemm_mma<0,256>, cudaFuncAttributeMaxDynamicSharedMemorySize, SM256);
    cudaFuncSetAttribute((const void*)gemm_mma<1,256>, cudaFuncAttributeMaxDynamicSharedMemorySize, SM256);
    cudaFuncSetAttribute((const void*)gemm_mma<2,256>, cudaFuncAttributeMaxDynamicSharedMemorySize, SM256);
    cudaFuncSetAttribute((const void*)gemm_mma<4,128>, cudaFuncAttributeMaxDynamicSharedMemorySize, SM128);

    // weight hi/lo splits + xdbc zero (independent)
    split4_kernel<<<(2*D_INNER*D_MODEL/4 + 255)/256, 256>>>((const float4*)in_proj_w,  inwh, inwl, 2*D_INNER*D_MODEL/4);
    split4_kernel<<<(96*D_INNER/4 + 255)/256, 256>>>((const float4*)x_proj_w,   xpwh, xpwl, 96*D_INNER/4);
    split4_kernel<<<(D_INNER*DT_RANK/4 + 255)/256, 256>>>((const float4*)dt_proj_w,  dtwh, dtwl, D_INNER*DT_RANK/4);
    split4_kernel<<<(D_MODEL*D_INNER/4 + 255)/256, 256>>>((const float4*)out_proj_w, opwh, opwl, D_MODEL*D_INNER/4);
    zero_kernel<<<(MROWS*96 + 255)/256, 256>>>(xdbc, MROWS*96);

    // 1. rmsnorm (+split)
    rmsnorm_kernel<<<MROWS, 256>>>(x, norm_w, xnh, xnl);

    // 2. in_proj: xz(4096,4096) = xn @ in_proj_w^T
    gemm_mma<0,256><<<dim3(16, 32, 1), 512, SM256>>>(xnh, xnl, inwh, inwl,
        D_MODEL, 2*D_INNER, 2*D_INNER, xz, nullptr, nullptr, nullptr);

    // 3. conv + silu (+split)
    conv_silu_kernel<<<(MROWS * (D_INNER/4) + 255)/256, 256>>>(conv_w, conv_b);

    // 4. x_proj (split-K=4, atomic accumulate into zeroed xdbc)
    gemm_mma<4,128><<<dim3(1, 32, 4), 512, SM128>>>(xch, xcl, xpwh, xpwl,
        D_INNER, 96, 96, xdbc, nullptr, nullptr, nullptr);

    // 4b. dt hi/lo split from xdbc[:, :64]
    dtsplit_kernel<<<(MROWS*DT_RANK + 255)/256, 256>>>();

    // 5. dt_proj + softplus/clip/du epilogue
    gemm_mma<1,256><<<dim3(8, 32, 1), 512, SM256>>>(dth, dtl, dtwh, dtwl,
        DT_RANK, D_INNER, D_INNER, dcb, dub, dt_proj_b, xconv);

    // 6. selective scan + (y + x_conv*D)*silu(z) (+split)
    scan_kernel<<<NB * (D_INNER/16), 256>>>(A_log, Dp);

    // 7. out_proj + residual
    gemm_mma<2,256><<<dim3(4, 32, 1), 512, SM256>>>(yh, yl, opwh, opwl,
        D_INNER, D_MODEL, D_MODEL, out, nullptr, x, nullptr);
}

// round 5
// speedup vs baseline: 1.5785x; 1.0546x over previous
#include <cuda_runtime.h>
#include <cuda_fp16.h>
#include <math.h>
#include <stdint.h>

#define D_MODEL 1024
#define D_INNER 2048
#define D_STATE 16
#define DT_RANK 64
#define NB 2
#define TSEQ 2048
#define MROWS (NB*TSEQ)   /* 4096 */
#define EPSV 1e-6f

typedef __half fp16;

// ---------------- scratch (no allocations allowed) ----------------
__device__ fp16  g_xnh[MROWS*D_MODEL],  g_xnl[MROWS*D_MODEL];
__device__ fp16  g_inwh[2*D_INNER*D_MODEL], g_inwl[2*D_INNER*D_MODEL];
__device__ fp16  g_xpwh[96*D_INNER],    g_xpwl[96*D_INNER];
__device__ fp16  g_dtwh[D_INNER*DT_RANK], g_dtwl[D_INNER*DT_RANK];
__device__ fp16  g_opwh[D_MODEL*D_INNER], g_opwl[D_MODEL*D_INNER];
__device__ float g_xz[MROWS*2*D_INNER];
__device__ float g_xconv[MROWS*D_INNER];
__device__ fp16  g_xch[MROWS*D_INNER],  g_xcl[MROWS*D_INNER];
__device__ float g_xdbc[MROWS*96];
__device__ fp16  g_dth[MROWS*DT_RANK],  g_dtl[MROWS*DT_RANK];
__device__ float g_dc[MROWS*D_INNER],   g_du[MROWS*D_INNER];
__device__ fp16  g_yh[MROWS*D_INNER],   g_yl[MROWS*D_INNER];

// ---------------- helpers ----------------
__device__ __forceinline__ uint32_t s2u(const void* p) {
    uint32_t a;
    asm("{ .reg .u64 t; cvta.to.shared.u64 t, %1; cvt.u32.u64 %0, t; }" : "=r"(a) : "l"(p));
    return a;
}
__device__ __forceinline__ void cpa16(uint32_t dst, const void* src) {
    asm volatile("cp.async.cg.shared.global [%0], [%1], 16;" :: "r"(dst), "l"(src) : "memory");
}
__device__ __forceinline__ void cpa16z(uint32_t dst, const void* src, int sz) {
    asm volatile("cp.async.cg.shared.global [%0], [%1], 16, %2;" :: "r"(dst), "l"(src), "r"(sz) : "memory");
}
#define CPA_COMMIT() asm volatile("cp.async.commit_group;" ::: "memory")

#define LDSM4(r, a) \
    asm volatile("ldmatrix.sync.aligned.m8n8.x4.shared.b16 {%0,%1,%2,%3}, [%4];" \
        : "=r"((r)[0]),"=r"((r)[1]),"=r"((r)[2]),"=r"((r)[3]) : "r"(a))

#define MMA16816(d, a, b0, b1) \
    asm volatile("mma.sync.aligned.m16n8k16.row.col.f32.f16.f16.f32 " \
        "{%0,%1,%2,%3}, {%4,%5,%6,%7}, {%8,%9}, {%0,%1,%2,%3};" \
        : "+f"((d)[0]),"+f"((d)[1]),"+f"((d)[2]),"+f"((d)[3]) \
        : "r"((a)[0]),"r"((a)[1]),"r"((a)[2]),"r"((a)[3]), "r"(b0),"r"(b1))

// ---------------- split-fp16 GEMM via mma.sync ----------------
// TERMS=3: Ah*Bh, Al*Bh, Ah*Bl  (err ~2^-24)
// TERMS=2: Ah*Bh, Al*Bh         (err ~2^-12 from B rounding)
// Tile: 128 x BN, BK=64 (128B rows, SW128 swizzle), 512 thr = 16 warps (4x4).
// EPI 0: C=v   EPI 1: dt epi   EPI 2: C=v+res   EPI 4: atomicAdd (split-K)
template<int EPI, int BN, int TERMS>
__global__ __launch_bounds__(512, 1)
void gemm_mma(const fp16* __restrict__ Ah, const fp16* __restrict__ Al,
              const fp16* __restrict__ Bh, const fp16* __restrict__ Bl,
              int K, int Nreal, int ldc,
              float* __restrict__ o0, float* __restrict__ o1,
              const float* __restrict__ e0, const float* __restrict__ e1)
{
    constexpr int STAGE = (128 + BN) * 128;   // bytes per stage
    constexpr int WN = BN / 4;                // warp n-width (64 or 32)
    constexpr int NJ = WN / 8;                // n8 groups per warp
    constexpr int BG = WN / 16;               // b ldsm groups
    extern __shared__ char dyn[];
    const uint32_t sbase = s2u(dyn);
    const int tid = threadIdx.x, lane = tid & 31, wid = tid >> 5;
    const int wm = wid >> 2, wn = wid & 3;    // 4 x 4 warp grid
    const int m0 = blockIdx.y * 128, n0 = blockIdx.x * BN;
    const int NCtot = TERMS * K / 64;
    const int per = (NCtot + gridDim.z - 1) / gridDim.z;
    const int kc0 = blockIdx.z * per;
    const int kc1 = min(NCtot, kc0 + per);

    float acc[2][NJ][4];
    #pragma unroll
    for (int i = 0; i < 2; i++)
        #pragma unroll
        for (int j = 0; j < NJ; j++)
            #pragma unroll
            for (int k = 0; k < 4; k++) acc[i][j][k] = 0.f;

    auto load_stage = [&](int s, int kc) {
        int kb = kc * 64;
        int seg = kb / K;
        int kk = kb - seg * K;
        const fp16* Asrc = (seg == 1) ? Al : Ah;
        const fp16* Bsrc = (seg == 2) ? Bl : Bh;
        uint32_t st = sbase + s * STAGE;
        #pragma unroll
        for (int j = 0; j < 2; j++) {                 // A: 1024 16B chunks
            int idx = tid + j * 512;
            int r = idx >> 3, c = idx & 7;
            cpa16(st + r * 128 + ((c ^ (r & 7)) * 16),
                  Asrc + (size_t)(m0 + r) * K + kk + c * 8);
        }
        uint32_t sb = st + 128 * 128;
        #pragma unroll
        for (int j = 0; j < BN / 64; j++) {           // B: BN*8 chunks
            int idx = tid + j * 512;
            int r = idx >> 3, c = idx & 7;
            int nr = n0 + r;
            int ok = nr < Nreal;
            cpa16z(sb + r * 128 + ((c ^ (r & 7)) * 16),
                   Bsrc + (size_t)(ok ? nr : 0) * K + kk + c * 8, ok ? 16 : 0);
        }
    };

    #pragma unroll
    for (int s = 0; s < 3; s++) {
        if (kc0 + s < kc1) load_stage(s, kc0 + s);
        CPA_COMMIT();
    }

    for (int kc = kc0; kc < kc1; kc++) {
        int i = kc - kc0;
        int s = i & 3;
        asm volatile("cp.async.wait_group 2;" ::: "memory");
        __syncthreads();
        if (kc + 3 < kc1) load_stage((i + 3) & 3, kc + 3);
        CPA_COMMIT();

        uint32_t sA = sbase + s * STAGE;
        uint32_t sB = sA + 128 * 128;
        #pragma unroll
        for (int ks = 0; ks < 4; ks++) {
            uint32_t a[2][4], b[BG][4];
            #pragma unroll
            for (int mi = 0; mi < 2; mi++) {
                int r = wm * 32 + mi * 16 + (lane & 15);
                int c = (2 * ks + (lane >> 4)) ^ (r & 7);
                LDSM4(a[mi], sA + r * 128 + c * 16);
            }
            #pragma unroll
            for (int g = 0; g < BG; g++) {
                int r = wn * WN + g * 16 + (lane & 7) + ((lane >> 4) & 1) * 8;
                int c = (2 * ks + ((lane >> 3) & 1)) ^ (r & 7);
                LDSM4(b[g], sB + r * 128 + c * 16);
            }
            #pragma unroll
            for (int mi = 0; mi < 2; mi++)
                #pragma unroll
                for (int nj = 0; nj < NJ; nj++) {
                    int bg = nj >> 1, br = (nj & 1) * 2;
                    MMA16816(acc[mi][nj], a[mi], b[bg][br], b[bg][br+1]);
                }
        }
    }

    // ---- epilogue straight from registers (float2 pairs) ----
    #pragma unroll
    for (int mi = 0; mi < 2; mi++)
        #pragma unroll
        for (int nj = 0; nj < NJ; nj++)
            #pragma unroll
            for (int h = 0; h < 2; h++) {
                int m = m0 + wm*32 + mi*16 + (lane >> 2) + h*8;
                int nb = n0 + wn*WN + nj*8 + (lane & 3)*2;
                float vx = acc[mi][nj][h*2], vy = acc[mi][nj][h*2+1];
                size_t ci = (size_t)m * ldc + nb;
                if (EPI == 0) {
                    *(float2*)(o0 + ci) = make_float2(vx, vy);
                } else if (EPI == 1) {
                    vx += e0[nb]; vy += e0[nb+1];
                    float spx = (vx > 20.f) ? vx : log1pf(__expf(vx));
                    float spy = (vy > 20.f) ? vy : log1pf(__expf(vy));
                    float dx = fminf(fmaxf(spx, -10.f), 1.f);
                    float dy = fminf(fmaxf(spy, -10.f), 1.f);
                    float2 ev = *(const float2*)(e1 + ci);
                    *(float2*)(o0 + ci) = make_float2(dx, dy);
                    *(float2*)(o1 + ci) = make_float2(dx * ev.x, dy * ev.y);
                } else if (EPI == 2) {
                    float2 rv = *(const float2*)(e0 + ci);
                    *(float2*)(o0 + ci) = make_float2(vx + rv.x, vy + rv.y);
                } else {
                    if (nb < Nreal) {
                        atomicAdd(o0 + ci, vx);
                        atomicAdd(o0 + ci + 1, vy);
                    }
                }
            }
}

// ---------------- hi/lo split of a float array ----------------
__global__ void split4_kernel(const float4* __restrict__ src,
                              fp16* __restrict__ hi, fp16* __restrict__ lo, int n4) {
    int i = blockIdx.x * 256 + threadIdx.x;
    if (i >= n4) return;
    float4 v = src[i];
    fp16 h0 = __float2half(v.x), h1 = __float2half(v.y);
    fp16 h2 = __float2half(v.z), h3 = __float2half(v.w);
    __half2 p0, p1, q0, q1;
    p0.x = h0; p0.y = h1; p1.x = h2; p1.y = h3;
    q0.x = __float2half(v.x - __half2float(h0));
    q0.y = __float2half(v.y - __half2float(h1));
    q1.x = __float2half(v.z - __half2float(h2));
    q1.y = __float2half(v.w - __half2float(h3));
    *(__half2*)(hi + (size_t)i * 4)     = p0;
    *(__half2*)(hi + (size_t)i * 4 + 2) = p1;
    *(__half2*)(lo + (size_t)i * 4)     = q0;
    *(__half2*)(lo + (size_t)i * 4 + 2) = q1;
}

__global__ void zero_kernel(float* __restrict__ p, int n) {
    int i = blockIdx.x * 256 + threadIdx.x;
    if (i < n) p[i] = 0.f;
}

__global__ void dtsplit_kernel() {
    int i = blockIdx.x * 256 + threadIdx.x;
    if (i >= MROWS * DT_RANK) return;
    int m = i >> 6, n = i & 63;
    float v = g_xdbc[(size_t)m * 96 + n];
    fp16 h = __float2half(v);
    g_dth[i] = h;
    g_dtl[i] = __float2half(v - __half2float(h));
}

// ---------------- RMSNorm -> split fp16 ----------------
__global__ void rmsnorm_kernel(const float* __restrict__ x,
                               const float* __restrict__ w,
                               fp16* __restrict__ oh, fp16* __restrict__ ol) {
    int row = blockIdx.x;
    int tid = threadIdx.x;
    const float4* xr = (const float4*)(x + (size_t)row * D_MODEL);
    float4 v = xr[tid];
    float ss = v.x*v.x + v.y*v.y + v.z*v.z + v.w*v.w;
    #pragma unroll
    for (int off = 16; off > 0; off >>= 1)
        ss += __shfl_xor_sync(0xffffffffu, ss, off);
    __shared__ float red[8];
    __shared__ float sscale;
    int lane = tid & 31, wq = tid >> 5;
    if (lane == 0) red[wq] = ss;
    __syncthreads();
    if (tid == 0) {
        float t = 0.f;
        #pragma unroll
        for (int i = 0; i < 8; i++) t += red[i];
        sscale = rsqrtf(t * (1.0f / D_MODEL) + EPSV);
    }
    __syncthreads();
    float sc = sscale;
    float4 wv = ((const float4*)w)[tid];
    float o0 = v.x*sc*wv.x, o1 = v.y*sc*wv.y, o2 = v.z*sc*wv.z, o3 = v.w*sc*wv.w;
    size_t base = (size_t)row * D_MODEL + tid * 4;
    fp16 h0=__float2half(o0), h1=__float2half(o1), h2=__float2half(o2), h3=__float2half(o3);
    __half2 ph0, ph1, pl0, pl1;
    ph0.x=h0; ph0.y=h1; ph1.x=h2; ph1.y=h3;
    pl0.x=__float2half(o0-__half2float(h0));
    pl0.y=__float2half(o1-__half2float(h1));
    pl1.x=__float2half(o2-__half2float(h2));
    pl1.y=__float2half(o3-__half2float(h3));
    *(__half2*)(oh+base)   = ph0; *(__half2*)(oh+base+2) = ph1;
    *(__half2*)(ol+base)   = pl0; *(__half2*)(ol+base+2) = pl1;
}

// ---------------- depthwise causal conv(4) + silu (+fp16 split) ----------------
__global__ void conv_silu_kernel(const float* __restrict__ cw,
                                 const float* __restrict__ cb) {
    int idx = blockIdx.x * 256 + threadIdx.x;
    if (idx >= MROWS * (D_INNER/4)) return;
    int d4 = idx & (D_INNER/4 - 1);
    int bt = idx >> 9;
    int t  = bt & (TSEQ - 1);
    int d  = d4 * 4;
    float wv[4][4];
    *(float4*)wv[0] = *(const float4*)(cw + (d+0)*4);
    *(float4*)wv[1] = *(const float4*)(cw + (d+1)*4);
    *(float4*)wv[2] = *(const float4*)(cw + (d+2)*4);
    *(float4*)wv[3] = *(const float4*)(cw + (d+3)*4);
    float4 bvv = *(const float4*)(cb + d);
    float a0 = bvv.x, a1 = bvv.y, a2 = bvv.z, a3 = bvv.w;
    #pragma unroll
    for (int k = 0; k < 4; k++) {
        int tt = t - 3 + k;
        if (tt < 0) continue;
        const float4 xv = *(const float4*)(g_xz + (size_t)(bt - t + tt) * (2*D_INNER) + d);
        a0 = fmaf(wv[0][k], xv.x, a0);
        a1 = fmaf(wv[1][k], xv.y, a1);
        a2 = fmaf(wv[2][k], xv.z, a2);
        a3 = fmaf(wv[3][k], xv.w, a3);
    }
    float o0 = a0/(1.f+__expf(-a0)), o1 = a1/(1.f+__expf(-a1));
    float o2 = a2/(1.f+__expf(-a2)), o3 = a3/(1.f+__expf(-a3));
    size_t base = (size_t)bt * D_INNER + d;
    *(float4*)(g_xconv + base) = make_float4(o0,o1,o2,o3);
    fp16 h0=__float2half(o0), h1=__float2half(o1), h2=__float2half(o2), h3=__float2half(o3);
    __half2 ph0, ph1, pl0, pl1;
    ph0.x=h0; ph0.y=h1; ph1.x=h2; ph1.y=h3;
    pl0.x=__float2half(o0-__half2float(h0));
    pl0.y=__float2half(o1-__half2float(h1));
    pl1.x=__float2half(o2-__half2float(h2));
    pl1.y=__float2half(o3-__half2float(h3));
    *(__half2*)(g_xch+base)   = ph0; *(__half2*)(g_xch+base+2) = ph1;
    *(__half2*)(g_xcl+base)   = pl0; *(__half2*)(g_xcl+base+2) = pl1;
}

// ---------------- selective scan + output epilogue ----------------
__global__ __launch_bounds__(256) void scan_kernel(const float* __restrict__ A_log,
                                                   const float* __restrict__ Dp) {
    __shared__ float sB[64*16], sC[64*16], sdc[64*16], sdu[64*16];
    int bid = blockIdx.x;
    int b = bid >> 7;
    int d0 = (bid & 127) << 4;
    int tid = threadIdx.x;
    int w = tid >> 5, lane = tid & 31;
    int s = lane & 15, half = lane >> 4;
    int cl = w * 2 + half;
    int d = d0 + cl;
    float Aval = -__expf(A_log[d * D_STATE + s]);
    float Dv = Dp[d];
    float h = 0.f;
    for (int t0 = 0; t0 < TSEQ; t0 += 64) {
        __syncthreads();
        for (int i = tid; i < 1024; i += 256) {
            int ti = i >> 4, j = i & 15;
            size_t row = (size_t)b * TSEQ + t0 + ti;
            sB[i]  = g_xdbc[row * 96 + 64 + j];
            sC[i]  = g_xdbc[row * 96 + 80 + j];
            sdc[i] = g_dc[row * D_INNER + d0 + j];
            sdu[i] = g_du[row * D_INNER + d0 + j];
        }
        __syncthreads();
        for (int i = 0; i < 64; i++) {
            float dcv = sdc[i*16 + cl];
            float duv = sdu[i*16 + cl];
            float r = __expf(dcv * Aval);
            h = fmaf(r, h, duv * sB[i*16 + s]);
            float p = h * sC[i*16 + s];
            p += __shfl_xor_sync(0xffffffffu, p, 8);
            p += __shfl_xor_sync(0xffffffffu, p, 4);
            p += __shfl_xor_sync(0xffffffffu, p, 2);
            p += __shfl_xor_sync(0xffffffffu, p, 1);
            if (s == 0) {
                size_t row = (size_t)b * TSEQ + t0 + i;
                float xc = g_xconv[row * D_INNER + d];
                float zv = g_xz[row * (2*D_INNER) + D_INNER + d];
                float sig = 1.f / (1.f + __expf(-zv));
                float yv = (p + xc * Dv) * (zv * sig);
                fp16 hh = __float2half(yv);
                g_yh[row * D_INNER + d] = hh;
                g_yl[row * D_INNER + d] = __float2half(yv - __half2float(hh));
            }
        }
    }
}

// ---------------- launch ----------------
#define SM256 ((128 + 256) * 128 * 4)   /* 196608 */
#define SM128 ((128 + 128) * 128 * 4)   /* 131072 */

extern "C" void kernel_launch(void* const* d_in, const int* in_sizes, int n_in,
                              void* d_out, int out_size) {
    (void)in_sizes; (void)n_in; (void)out_size;
    const float* x          = (const float*)d_in[0];
    const float* in_proj_w  = (const float*)d_in[1];
    const float* conv_w     = (const float*)d_in[2];
    const float* conv_b     = (const float*)d_in[3];
    const float* x_proj_w   = (const float*)d_in[4];
    const float* dt_proj_w  = (const float*)d_in[5];
    const float* dt_proj_b  = (const float*)d_in[6];
    const float* A_log      = (const float*)d_in[7];
    const float* Dp         = (const float*)d_in[8];
    const float* out_proj_w = (const float*)d_in[9];
    const float* norm_w     = (const float*)d_in[10];
    float* out = (float*)d_out;

    fp16 *xnh, *xnl, *inwh, *inwl, *xpwh, *xpwl, *dtwh, *dtwl, *opwh, *opwl;
    fp16 *xch, *xcl, *dth, *dtl, *yh, *yl;
    float *xz, *xconv, *xdbc, *dcb, *dub;
    cudaGetSymbolAddress((void**)&xnh,  g_xnh);  cudaGetSymbolAddress((void**)&xnl,  g_xnl);
    cudaGetSymbolAddress((void**)&inwh, g_inwh); cudaGetSymbolAddress((void**)&inwl, g_inwl);
    cudaGetSymbolAddress((void**)&xpwh, g_xpwh); cudaGetSymbolAddress((void**)&xpwl, g_xpwl);
    cudaGetSymbolAddress((void**)&dtwh, g_dtwh); cudaGetSymbolAddress((void**)&dtwl, g_dtwl);
    cudaGetSymbolAddress((void**)&opwh, g_opwh); cudaGetSymbolAddress((void**)&opwl, g_opwl);
    cudaGetSymbolAddress((void**)&xch,  g_xch);  cudaGetSymbolAddress((void**)&xcl,  g_xcl);
    cudaGetSymbolAddress((void**)&dth,  g_dth);  cudaGetSymbolAddress((void**)&dtl,  g_dtl);
    cudaGetSymbolAddress((void**)&yh,   g_yh);   cudaGetSymbolAddress((void**)&yl,   g_yl);
    cudaGetSymbolAddress((void**)&xz,    g_xz);
    cudaGetSymbolAddress((void**)&xconv, g_xconv);
    cudaGetSymbolAddress((void**)&xdbc,  g_xdbc);
    cudaGetSymbolAddress((void**)&dcb,   g_dc);
    cudaGetSymbolAddress((void**)&dub,   g_du);

    cudaFuncSetAttribute((const void*)gemm_mma<0,256,2>, cudaFuncAttributeMaxDynamicSharedMemorySize, SM256);
    cudaFuncSetAttribute((const void*)gemm_mma<1,256,3>, cudaFuncAttributeMaxDynamicSharedMemorySize, SM256);
    cudaFuncSetAttribute((const void*)gemm_mma<2,256,2>, cudaFuncAttributeMaxDynamicSharedMemorySize, SM256);
    cudaFuncSetAttribute((const void*)gemm_mma<4,128,3>, cudaFuncAttributeMaxDynamicSharedMemorySize, SM128);

    // weight hi/lo splits + xdbc zero (independent)
    split4_kernel<<<(2*D_INNER*D_MODEL/4 + 255)/256, 256>>>((const float4*)in_proj_w,  inwh, inwl, 2*D_INNER*D_MODEL/4);
    split4_kernel<<<(96*D_INNER/4 + 255)/256, 256>>>((const float4*)x_proj_w,   xpwh, xpwl, 96*D_INNER/4);
    split4_kernel<<<(D_INNER*DT_RANK/4 + 255)/256, 256>>>((const float4*)dt_proj_w,  dtwh, dtwl, D_INNER*DT_RANK/4);
    split4_kernel<<<(D_MODEL*D_INNER/4 + 255)/256, 256>>>((const float4*)out_proj_w, opwh, opwl, D_MODEL*D_INNER/4);
    zero_kernel<<<(MROWS*96 + 255)/256, 256>>>(xdbc, MROWS*96);

    // 1. rmsnorm (+split)
    rmsnorm_kernel<<<MROWS, 256>>>(x, norm_w, xnh, xnl);

    // 2. in_proj (2-term: A split, W single fp16)
    gemm_mma<0,256,2><<<dim3(16, 32, 1), 512, SM256>>>(xnh, xnl, inwh, inwl,
        D_MODEL, 2*D_INNER, 2*D_INNER, xz, nullptr, nullptr, nullptr);

    // 3. conv + silu (+split)
    conv_silu_kernel<<<(MROWS * (D_INNER/4) + 255)/256, 256>>>(conv_w, conv_b);

    // 4. x_proj (3-term, split-K=4, atomic accumulate into zeroed xdbc)
    gemm_mma<4,128,3><<<dim3(1, 32, 4), 512, SM128>>>(xch, xcl, xpwh, xpwl,
        D_INNER, 96, 96, xdbc, nullptr, nullptr, nullptr);

    // 4b. dt hi/lo split from xdbc[:, :64]
    dtsplit_kernel<<<(MROWS*DT_RANK + 255)/256, 256>>>();

    // 5. dt_proj (3-term) + softplus/clip/du epilogue
    gemm_mma<1,256,3><<<dim3(8, 32, 1), 512, SM256>>>(dth, dtl, dtwh, dtwl,
        DT_RANK, D_INNER, D_INNER, dcb, dub, dt_proj_b, xconv);

    // 6. selective scan + (y + x_conv*D)*silu(z) (+split)
    scan_kernel<<<NB * (D_INNER/16), 256>>>(A_log, Dp);

    // 7. out_proj (2-term) + residual
    gemm_mma<2,256,2><<<dim3(4, 32, 1), 512, SM256>>>(yh, yl, opwh, opwl,
        D_INNER, D_MODEL, D_MODEL, out, nullptr, x, nullptr);
}

// round 6
// speedup vs baseline: 4.6192x; 2.9264x over previous
#include <cuda_runtime.h>
#include <cuda_fp16.h>
#include <math.h>
#include <stdint.h>

#define D_MODEL 1024
#define D_INNER 2048
#define D_STATE 16
#define DT_RANK 64
#define NB 2
#define TSEQ 2048
#define MROWS (NB*TSEQ)   /* 4096 */
#define EPSV 1e-6f

typedef __half fp16;

// ---------------- scratch (no allocations allowed) ----------------
__device__ fp16  g_xnh[MROWS*D_MODEL],  g_xnl[MROWS*D_MODEL];
__device__ fp16  g_inwh[2*D_INNER*D_MODEL], g_inwl[2*D_INNER*D_MODEL];
__device__ fp16  g_xpwh[96*D_INNER],    g_xpwl[96*D_INNER];
__device__ fp16  g_dtwh[D_INNER*DT_RANK], g_dtwl[D_INNER*DT_RANK];
__device__ fp16  g_opwh[D_MODEL*D_INNER], g_opwl[D_MODEL*D_INNER];
__device__ float g_xz[MROWS*2*D_INNER];
__device__ float g_xconv[MROWS*D_INNER];
__device__ fp16  g_xch[MROWS*D_INNER],  g_xcl[MROWS*D_INNER];
__device__ float g_xdbc[MROWS*96];
__device__ fp16  g_dth[MROWS*DT_RANK],  g_dtl[MROWS*DT_RANK];
__device__ float g_dc[MROWS*D_INNER],   g_du[MROWS*D_INNER];
__device__ fp16  g_yh[MROWS*D_INNER],   g_yl[MROWS*D_INNER];

// ---------------- helpers ----------------
__device__ __forceinline__ uint32_t s2u(const void* p) {
    uint32_t a;
    asm("{ .reg .u64 t; cvta.to.shared.u64 t, %1; cvt.u32.u64 %0, t; }" : "=r"(a) : "l"(p));
    return a;
}
__device__ __forceinline__ void cpa16(uint32_t dst, const void* src) {
    asm volatile("cp.async.cg.shared.global [%0], [%1], 16;" :: "r"(dst), "l"(src) : "memory");
}
__device__ __forceinline__ void cpa16z(uint32_t dst, const void* src, int sz) {
    asm volatile("cp.async.cg.shared.global [%0], [%1], 16, %2;" :: "r"(dst), "l"(src), "r"(sz) : "memory");
}
#define CPA_COMMIT() asm volatile("cp.async.commit_group;" ::: "memory")

#define LDSM4(r, a) \
    asm volatile("ldmatrix.sync.aligned.m8n8.x4.shared.b16 {%0,%1,%2,%3}, [%4];" \
        : "=r"((r)[0]),"=r"((r)[1]),"=r"((r)[2]),"=r"((r)[3]) : "r"(a))

#define MMA16816(d, a, b0, b1) \
    asm volatile("mma.sync.aligned.m16n8k16.row.col.f32.f16.f16.f32 " \
        "{%0,%1,%2,%3}, {%4,%5,%6,%7}, {%8,%9}, {%0,%1,%2,%3};" \
        : "+f"((d)[0]),"+f"((d)[1]),"+f"((d)[2]),"+f"((d)[3]) \
        : "r"((a)[0]),"r"((a)[1]),"r"((a)[2]),"r"((a)[3]), "r"(b0),"r"(b1))

// ---------------- split-fp16 GEMM via mma.sync (unchanged from R5) ----------------
template<int EPI, int BN, int TERMS>
__global__ __launch_bounds__(512, 1)
void gemm_mma(const fp16* __restrict__ Ah, const fp16* __restrict__ Al,
              const fp16* __restrict__ Bh, const fp16* __restrict__ Bl,
              int K, int Nreal, int ldc,
              float* __restrict__ o0, float* __restrict__ o1,
              const float* __restrict__ e0, const float* __restrict__ e1)
{
    constexpr int STAGE = (128 + BN) * 128;
    constexpr int WN = BN / 4;
    constexpr int NJ = WN / 8;
    constexpr int BG = WN / 16;
    extern __shared__ char dyn[];
    const uint32_t sbase = s2u(dyn);
    const int tid = threadIdx.x, lane = tid & 31, wid = tid >> 5;
    const int wm = wid >> 2, wn = wid & 3;
    const int m0 = blockIdx.y * 128, n0 = blockIdx.x * BN;
    const int NCtot = TERMS * K / 64;
    const int per = (NCtot + gridDim.z - 1) / gridDim.z;
    const int kc0 = blockIdx.z * per;
    const int kc1 = min(NCtot, kc0 + per);

    float acc[2][NJ][4];
    #pragma unroll
    for (int i = 0; i < 2; i++)
        #pragma unroll
        for (int j = 0; j < NJ; j++)
            #pragma unroll
            for (int k = 0; k < 4; k++) acc[i][j][k] = 0.f;

    auto load_stage = [&](int s, int kc) {
        int kb = kc * 64;
        int seg = kb / K;
        int kk = kb - seg * K;
        const fp16* Asrc = (seg == 1) ? Al : Ah;
        const fp16* Bsrc = (seg == 2) ? Bl : Bh;
        uint32_t st = sbase + s * STAGE;
        #pragma unroll
        for (int j = 0; j < 2; j++) {
            int idx = tid + j * 512;
            int r = idx >> 3, c = idx & 7;
            cpa16(st + r * 128 + ((c ^ (r & 7)) * 16),
                  Asrc + (size_t)(m0 + r) * K + kk + c * 8);
        }
        uint32_t sb = st + 128 * 128;
        #pragma unroll
        for (int j = 0; j < BN / 64; j++) {
            int idx = tid + j * 512;
            int r = idx >> 3, c = idx & 7;
            int nr = n0 + r;
            int ok = nr < Nreal;
            cpa16z(sb + r * 128 + ((c ^ (r & 7)) * 16),
                   Bsrc + (size_t)(ok ? nr : 0) * K + kk + c * 8, ok ? 16 : 0);
        }
    };

    #pragma unroll
    for (int s = 0; s < 3; s++) {
        if (kc0 + s < kc1) load_stage(s, kc0 + s);
        CPA_COMMIT();
    }

    for (int kc = kc0; kc < kc1; kc++) {
        int i = kc - kc0;
        int s = i & 3;
        asm volatile("cp.async.wait_group 2;" ::: "memory");
        __syncthreads();
        if (kc + 3 < kc1) load_stage((i + 3) & 3, kc + 3);
        CPA_COMMIT();

        uint32_t sA = sbase + s * STAGE;
        uint32_t sB = sA + 128 * 128;
        #pragma unroll
        for (int ks = 0; ks < 4; ks++) {
            uint32_t a[2][4], b[BG][4];
            #pragma unroll
            for (int mi = 0; mi < 2; mi++) {
                int r = wm * 32 + mi * 16 + (lane & 15);
                int c = (2 * ks + (lane >> 4)) ^ (r & 7);
                LDSM4(a[mi], sA + r * 128 + c * 16);
            }
            #pragma unroll
            for (int g = 0; g < BG; g++) {
                int r = wn * WN + g * 16 + (lane & 7) + ((lane >> 4) & 1) * 8;
                int c = (2 * ks + ((lane >> 3) & 1)) ^ (r & 7);
                LDSM4(b[g], sB + r * 128 + c * 16);
            }
            #pragma unroll
            for (int mi = 0; mi < 2; mi++)
                #pragma unroll
                for (int nj = 0; nj < NJ; nj++) {
                    int bg = nj >> 1, br = (nj & 1) * 2;
                    MMA16816(acc[mi][nj], a[mi], b[bg][br], b[bg][br+1]);
                }
        }
    }

    #pragma unroll
    for (int mi = 0; mi < 2; mi++)
        #pragma unroll
        for (int nj = 0; nj < NJ; nj++)
            #pragma unroll
            for (int h = 0; h < 2; h++) {
                int m = m0 + wm*32 + mi*16 + (lane >> 2) + h*8;
                int nb = n0 + wn*WN + nj*8 + (lane & 3)*2;
                float vx = acc[mi][nj][h*2], vy = acc[mi][nj][h*2+1];
                size_t ci = (size_t)m * ldc + nb;
                if (EPI == 0) {
                    *(float2*)(o0 + ci) = make_float2(vx, vy);
                } else if (EPI == 1) {
                    vx += e0[nb]; vy += e0[nb+1];
                    float spx = (vx > 20.f) ? vx : log1pf(__expf(vx));
                    float spy = (vy > 20.f) ? vy : log1pf(__expf(vy));
                    float dx = fminf(fmaxf(spx, -10.f), 1.f);
                    float dy = fminf(fmaxf(spy, -10.f), 1.f);
                    float2 ev = *(const float2*)(e1 + ci);
                    *(float2*)(o0 + ci) = make_float2(dx, dy);
                    *(float2*)(o1 + ci) = make_float2(dx * ev.x, dy * ev.y);
                } else if (EPI == 2) {
                    float2 rv = *(const float2*)(e0 + ci);
                    *(float2*)(o0 + ci) = make_float2(vx + rv.x, vy + rv.y);
                } else {
                    if (nb < Nreal) {
                        atomicAdd(o0 + ci, vx);
                        atomicAdd(o0 + ci + 1, vy);
                    }
                }
            }
}

// ---------------- hi/lo split of a float array ----------------
__global__ void split4_kernel(const float4* __restrict__ src,
                              fp16* __restrict__ hi, fp16* __restrict__ lo, int n4) {
    int i = blockIdx.x * 256 + threadIdx.x;
    if (i >= n4) return;
    float4 v = src[i];
    fp16 h0 = __float2half(v.x), h1 = __float2half(v.y);
    fp16 h2 = __float2half(v.z), h3 = __float2half(v.w);
    __half2 p0, p1, q0, q1;
    p0.x = h0; p0.y = h1; p1.x = h2; p1.y = h3;
    q0.x = __float2half(v.x - __half2float(h0));
    q0.y = __float2half(v.y - __half2float(h1));
    q1.x = __float2half(v.z - __half2float(h2));
    q1.y = __float2half(v.w - __half2float(h3));
    *(__half2*)(hi + (size_t)i * 4)     = p0;
    *(__half2*)(hi + (size_t)i * 4 + 2) = p1;
    *(__half2*)(lo + (size_t)i * 4)     = q0;
    *(__half2*)(lo + (size_t)i * 4 + 2) = q1;
}

__global__ void zero_kernel(float* __restrict__ p, int n) {
    int i = blockIdx.x * 256 + threadIdx.x;
    if (i < n) p[i] = 0.f;
}

__global__ void dtsplit_kernel() {
    int i = blockIdx.x * 256 + threadIdx.x;
    if (i >= MROWS * DT_RANK) return;
    int m = i >> 6, n = i & 63;
    float v = g_xdbc[(size_t)m * 96 + n];
    fp16 h = __float2half(v);
    g_dth[i] = h;
    g_dtl[i] = __float2half(v - __half2float(h));
}

// ---------------- RMSNorm -> split fp16 ----------------
__global__ void rmsnorm_kernel(const float* __restrict__ x,
                               const float* __restrict__ w,
                               fp16* __restrict__ oh, fp16* __restrict__ ol) {
    int row = blockIdx.x;
    int tid = threadIdx.x;
    const float4* xr = (const float4*)(x + (size_t)row * D_MODEL);
    float4 v = xr[tid];
    float ss = v.x*v.x + v.y*v.y + v.z*v.z + v.w*v.w;
    #pragma unroll
    for (int off = 16; off > 0; off >>= 1)
        ss += __shfl_xor_sync(0xffffffffu, ss, off);
    __shared__ float red[8];
    __shared__ float sscale;
    int lane = tid & 31, wq = tid >> 5;
    if (lane == 0) red[wq] = ss;
    __syncthreads();
    if (tid == 0) {
        float t = 0.f;
        #pragma unroll
        for (int i = 0; i < 8; i++) t += red[i];
        sscale = rsqrtf(t * (1.0f / D_MODEL) + EPSV);
    }
    __syncthreads();
    float sc = sscale;
    float4 wv = ((const float4*)w)[tid];
    float o0 = v.x*sc*wv.x, o1 = v.y*sc*wv.y, o2 = v.z*sc*wv.z, o3 = v.w*sc*wv.w;
    size_t base = (size_t)row * D_MODEL + tid * 4;
    fp16 h0=__float2half(o0), h1=__float2half(o1), h2=__float2half(o2), h3=__float2half(o3);
    __half2 ph0, ph1, pl0, pl1;
    ph0.x=h0; ph0.y=h1; ph1.x=h2; ph1.y=h3;
    pl0.x=__float2half(o0-__half2float(h0));
    pl0.y=__float2half(o1-__half2float(h1));
    pl1.x=__float2half(o2-__half2float(h2));
    pl1.y=__float2half(o3-__half2float(h3));
    *(__half2*)(oh+base)   = ph0; *(__half2*)(oh+base+2) = ph1;
    *(__half2*)(ol+base)   = pl0; *(__half2*)(ol+base+2) = pl1;
}

// ---------------- depthwise causal conv(4) + silu (+fp16 split) ----------------
__global__ void conv_silu_kernel(const float* __restrict__ cw,
                                 const float* __restrict__ cb) {
    int idx = blockIdx.x * 256 + threadIdx.x;
    if (idx >= MROWS * (D_INNER/4)) return;
    int d4 = idx & (D_INNER/4 - 1);
    int bt = idx >> 9;
    int t  = bt & (TSEQ - 1);
    int d  = d4 * 4;
    float wv[4][4];
    *(float4*)wv[0] = *(const float4*)(cw + (d+0)*4);
    *(float4*)wv[1] = *(const float4*)(cw + (d+1)*4);
    *(float4*)wv[2] = *(const float4*)(cw + (d+2)*4);
    *(float4*)wv[3] = *(const float4*)(cw + (d+3)*4);
    float4 bvv = *(const float4*)(cb + d);
    float a0 = bvv.x, a1 = bvv.y, a2 = bvv.z, a3 = bvv.w;
    #pragma unroll
    for (int k = 0; k < 4; k++) {
        int tt = t - 3 + k;
        if (tt < 0) continue;
        const float4 xv = *(const float4*)(g_xz + (size_t)(bt - t + tt) * (2*D_INNER) + d);
        a0 = fmaf(wv[0][k], xv.x, a0);
        a1 = fmaf(wv[1][k], xv.y, a1);
        a2 = fmaf(wv[2][k], xv.z, a2);
        a3 = fmaf(wv[3][k], xv.w, a3);
    }
    float o0 = a0/(1.f+__expf(-a0)), o1 = a1/(1.f+__expf(-a1));
    float o2 = a2/(1.f+__expf(-a2)), o3 = a3/(1.f+__expf(-a3));
    size_t base = (size_t)bt * D_INNER + d;
    *(float4*)(g_xconv + base) = make_float4(o0,o1,o2,o3);
    fp16 h0=__float2half(o0), h1=__float2half(o1), h2=__float2half(o2), h3=__float2half(o3);
    __half2 ph0, ph1, pl0, pl1;
    ph0.x=h0; ph0.y=h1; ph1.x=h2; ph1.y=h3;
    pl0.x=__float2half(o0-__half2float(h0));
    pl0.y=__float2half(o1-__half2float(h1));
    pl1.x=__float2half(o2-__half2float(h2));
    pl1.y=__float2half(o3-__half2float(h3));
    *(__half2*)(g_xch+base)   = ph0; *(__half2*)(g_xch+base+2) = ph1;
    *(__half2*)(g_xcl+base)   = pl0; *(__half2*)(g_xcl+base+2) = pl1;
}

// ---------------- selective scan: latency-optimized ----------------
// All gmem staged in smem during parallel load phase (incl. xc*D and silu(z)).
// Serial loop: 3 LDS + 1 exp + 2 FMA + 1 STS per step, no shfl, no gmem.
// Every 16 steps: parallel reduction over states + epilogue store.
__global__ __launch_bounds__(256) void scan_kernel(const float* __restrict__ A_log,
                                                   const float* __restrict__ Dp) {
    __shared__ float sB[64*16], sC[64*16], sdc[64*16], sdu[64*16];
    __shared__ float se[64*16], sg[64*16];
    __shared__ float sP[16*16*17];        // [t16][cl][s] padded
    int bid = blockIdx.x;
    int b = bid >> 7;
    int d0 = (bid & 127) << 4;
    int tid = threadIdx.x;
    int w = tid >> 5, lane = tid & 31;
    int s = lane & 15, half = lane >> 4;
    int cl = w * 2 + half;                // channel-local 0..15
    int d = d0 + cl;
    int jlo = tid & 15;                   // load-phase channel (i & 15 == tid & 15)
    int tl_r = tid >> 4, cl_r = tid & 15; // reduction mapping
    float Aval = -__expf(A_log[d * D_STATE + s]);
    float Dvj = Dp[d0 + jlo];
    float h = 0.f;

    for (int t0 = 0; t0 < TSEQ; t0 += 64) {
        // ---- parallel staging ----
        for (int i = tid; i < 1024; i += 256) {
            int ti = i >> 4, j = i & 15;
            size_t row = (size_t)b * TSEQ + t0 + ti;
            sB[i]  = g_xdbc[row * 96 + 64 + j];
            sC[i]  = g_xdbc[row * 96 + 80 + j];
            sdc[i] = g_dc[row * D_INNER + d0 + j];
            sdu[i] = g_du[row * D_INNER + d0 + j];
            se[i]  = g_xconv[row * D_INNER + d0 + j] * Dvj;
            float zv = g_xz[row * (2*D_INNER) + D_INNER + d0 + j];
            sg[i]  = zv / (1.f + __expf(-zv));
        }
        __syncthreads();
        #pragma unroll
        for (int sub = 0; sub < 4; sub++) {
            // ---- serial phase: 16 steps, pure smem/reg ----
            #pragma unroll
            for (int i = 0; i < 16; i++) {
                int t = sub * 16 + i;
                float dcv = sdc[t*16 + cl];
                float duv = sdu[t*16 + cl];
                float r = __expf(dcv * Aval);
                h = fmaf(r, h, duv * sB[t*16 + s]);
                sP[(i*16 + cl)*17 + s] = h * sC[t*16 + s];
            }
            __syncthreads();
            // ---- parallel reduction + epilogue ----
            {
                float p = 0.f;
                int base = (tl_r*16 + cl_r)*17;
                #pragma unroll
                for (int q = 0; q < 16; q++) p += sP[base + q];
                int t = sub * 16 + tl_r;
                float yv = (p + se[t*16 + cl_r]) * sg[t*16 + cl_r];
                size_t row = (size_t)b * TSEQ + t0 + t;
                fp16 hh = __float2half(yv);
                g_yh[row * D_INNER + d0 + cl_r] = hh;
                g_yl[row * D_INNER + d0 + cl_r] = __float2half(yv - __half2float(hh));
            }
            __syncthreads();
        }
    }
}

// ---------------- launch ----------------
#define SM256 ((128 + 256) * 128 * 4)   /* 196608 */
#define SM128 ((128 + 128) * 128 * 4)   /* 131072 */

extern "C" void kernel_launch(void* const* d_in, const int* in_sizes, int n_in,
                              void* d_out, int out_size) {
    (void)in_sizes; (void)n_in; (void)out_size;
    const float* x          = (const float*)d_in[0];
    const float* in_proj_w  = (const float*)d_in[1];
    const float* conv_w     = (const float*)d_in[2];
    const float* conv_b     = (const float*)d_in[3];
    const float* x_proj_w   = (const float*)d_in[4];
    const float* dt_proj_w  = (const float*)d_in[5];
    const float* dt_proj_b  = (const float*)d_in[6];
    const float* A_log      = (const float*)d_in[7];
    const float* Dp         = (const float*)d_in[8];
    const float* out_proj_w = (const float*)d_in[9];
    const float* norm_w     = (const float*)d_in[10];
    float* out = (float*)d_out;

    fp16 *xnh, *xnl, *inwh, *inwl, *xpwh, *xpwl, *dtwh, *dtwl, *opwh, *opwl;
    fp16 *xch, *xcl, *dth, *dtl, *yh, *yl;
    float *xz, *xconv, *xdbc, *dcb, *dub;
    cudaGetSymbolAddress((void**)&xnh,  g_xnh);  cudaGetSymbolAddress((void**)&xnl,  g_xnl);
    cudaGetSymbolAddress((void**)&inwh, g_inwh); cudaGetSymbolAddress((void**)&inwl, g_inwl);
    cudaGetSymbolAddress((void**)&xpwh, g_xpwh); cudaGetSymbolAddress((void**)&xpwl, g_xpwl);
    cudaGetSymbolAddress((void**)&dtwh, g_dtwh); cudaGetSymbolAddress((void**)&dtwl, g_dtwl);
    cudaGetSymbolAddress((void**)&opwh, g_opwh); cudaGetSymbolAddress((void**)&opwl, g_opwl);
    cudaGetSymbolAddress((void**)&xch,  g_xch);  cudaGetSymbolAddress((void**)&xcl,  g_xcl);
    cudaGetSymbolAddress((void**)&dth,  g_dth);  cudaGetSymbolAddress((void**)&dtl,  g_dtl);
    cudaGetSymbolAddress((void**)&yh,   g_yh);   cudaGetSymbolAddress((void**)&yl,   g_yl);
    cudaGetSymbolAddress((void**)&xz,    g_xz);
    cudaGetSymbolAddress((void**)&xconv, g_xconv);
    cudaGetSymbolAddress((void**)&xdbc,  g_xdbc);
    cudaGetSymbolAddress((void**)&dcb,   g_dc);
    cudaGetSymbolAddress((void**)&dub,   g_du);

    cudaFuncSetAttribute((const void*)gemm_mma<0,256,2>, cudaFuncAttributeMaxDynamicSharedMemorySize, SM256);
    cudaFuncSetAttribute((const void*)gemm_mma<1,256,3>, cudaFuncAttributeMaxDynamicSharedMemorySize, SM256);
    cudaFuncSetAttribute((const void*)gemm_mma<2,256,2>, cudaFuncAttributeMaxDynamicSharedMemorySize, SM256);
    cudaFuncSetAttribute((const void*)gemm_mma<4,128,3>, cudaFuncAttributeMaxDynamicSharedMemorySize, SM128);

    // weight hi/lo splits + xdbc zero (independent)
    split4_kernel<<<(2*D_INNER*D_MODEL/4 + 255)/256, 256>>>((const float4*)in_proj_w,  inwh, inwl, 2*D_INNER*D_MODEL/4);
    split4_kernel<<<(96*D_INNER/4 + 255)/256, 256>>>((const float4*)x_proj_w,   xpwh, xpwl, 96*D_INNER/4);
    split4_kernel<<<(D_INNER*DT_RANK/4 + 255)/256, 256>>>((const float4*)dt_proj_w,  dtwh, dtwl, D_INNER*DT_RANK/4);
    split4_kernel<<<(D_MODEL*D_INNER/4 + 255)/256, 256>>>((const float4*)out_proj_w, opwh, opwl, D_MODEL*D_INNER/4);
    zero_kernel<<<(MROWS*96 + 255)/256, 256>>>(xdbc, MROWS*96);

    // 1. rmsnorm (+split)
    rmsnorm_kernel<<<MROWS, 256>>>(x, norm_w, xnh, xnl);

    // 2. in_proj (2-term)
    gemm_mma<0,256,2><<<dim3(16, 32, 1), 512, SM256>>>(xnh, xnl, inwh, inwl,
        D_MODEL, 2*D_INNER, 2*D_INNER, xz, nullptr, nullptr, nullptr);

    // 3. conv + silu (+split)
    conv_silu_kernel<<<(MROWS * (D_INNER/4) + 255)/256, 256>>>(conv_w, conv_b);

    // 4. x_proj (3-term, split-K=4)
    gemm_mma<4,128,3><<<dim3(1, 32, 4), 512, SM128>>>(xch, xcl, xpwh, xpwl,
        D_INNER, 96, 96, xdbc, nullptr, nullptr, nullptr);

    // 4b. dt hi/lo split
    dtsplit_kernel<<<(MROWS*DT_RANK + 255)/256, 256>>>();

    // 5. dt_proj (3-term) + softplus/clip/du epilogue
    gemm_mma<1,256,3><<<dim3(8, 32, 1), 512, SM256>>>(dth, dtl, dtwh, dtwl,
        DT_RANK, D_INNER, D_INNER, dcb, dub, dt_proj_b, xconv);

    // 6. selective scan (latency-optimized)
    scan_kernel<<<NB * (D_INNER/16), 256>>>(A_log, Dp);

    // 7. out_proj (2-term) + residual
    gemm_mma<2,256,2><<<dim3(4, 32, 1), 512, SM256>>>(yh, yl, opwh, opwl,
        D_INNER, D_MODEL, D_MODEL, out, nullptr, x, nullptr);
}

// round 7
// speedup vs baseline: 6.1940x; 1.3409x over previous
#include <cuda_runtime.h>
#include <cuda_fp16.h>
#include <math.h>
#include <stdint.h>

#define D_MODEL 1024
#define D_INNER 2048
#define D_STATE 16
#define DT_RANK 64
#define NB 2
#define TSEQ 2048
#define MROWS (NB*TSEQ)   /* 4096 */
#define EPSV 1e-6f

typedef __half fp16;

// ---------------- scratch (no allocations allowed) ----------------
__device__ fp16  g_xnh[MROWS*D_MODEL];
__device__ fp16  g_inwh[2*D_INNER*D_MODEL];
__device__ fp16  g_xpwh[96*D_INNER],    g_xpwl[96*D_INNER];
__device__ fp16  g_dtwh[D_INNER*DT_RANK], g_dtwl[D_INNER*DT_RANK];
__device__ fp16  g_opwh[D_MODEL*D_INNER];
__device__ float g_xz[MROWS*2*D_INNER];
__device__ float g_xconv[MROWS*D_INNER];
__device__ fp16  g_xch[MROWS*D_INNER],  g_xcl[MROWS*D_INNER];
__device__ float g_xdbc[MROWS*96];
__device__ fp16  g_dth[MROWS*DT_RANK],  g_dtl[MROWS*DT_RANK];
__device__ float g_dc[MROWS*D_INNER],   g_du[MROWS*D_INNER];
__device__ fp16  g_yh[MROWS*D_INNER];

// ---------------- helpers ----------------
__device__ __forceinline__ uint32_t s2u(const void* p) {
    uint32_t a;
    asm("{ .reg .u64 t; cvta.to.shared.u64 t, %1; cvt.u32.u64 %0, t; }" : "=r"(a) : "l"(p));
    return a;
}
__device__ __forceinline__ void cpa16(uint32_t dst, const void* src) {
    asm volatile("cp.async.cg.shared.global [%0], [%1], 16;" :: "r"(dst), "l"(src) : "memory");
}
__device__ __forceinline__ void cpa16z(uint32_t dst, const void* src, int sz) {
    asm volatile("cp.async.cg.shared.global [%0], [%1], 16, %2;" :: "r"(dst), "l"(src), "r"(sz) : "memory");
}
#define CPA_COMMIT() asm volatile("cp.async.commit_group;" ::: "memory")

#define LDSM4(r, a) \
    asm volatile("ldmatrix.sync.aligned.m8n8.x4.shared.b16 {%0,%1,%2,%3}, [%4];" \
        : "=r"((r)[0]),"=r"((r)[1]),"=r"((r)[2]),"=r"((r)[3]) : "r"(a))

#define MMA16816(d, a, b0, b1) \
    asm volatile("mma.sync.aligned.m16n8k16.row.col.f32.f16.f16.f32 " \
        "{%0,%1,%2,%3}, {%4,%5,%6,%7}, {%8,%9}, {%0,%1,%2,%3};" \
        : "+f"((d)[0]),"+f"((d)[1]),"+f"((d)[2]),"+f"((d)[3]) \
        : "r"((a)[0]),"r"((a)[1]),"r"((a)[2]),"r"((a)[3]), "r"(b0),"r"(b1))

// ---------------- split-fp16 GEMM via mma.sync ----------------
// TERMS=1: Ah*Bh     TERMS=3: Ah*Bh, Al*Bh, Ah*Bl
template<int EPI, int BN, int TERMS>
__global__ __launch_bounds__(512, 1)
void gemm_mma(const fp16* __restrict__ Ah, const fp16* __restrict__ Al,
              const fp16* __restrict__ Bh, const fp16* __restrict__ Bl,
              int K, int Nreal, int ldc,
              float* __restrict__ o0, float* __restrict__ o1,
              const float* __restrict__ e0, const float* __restrict__ e1)
{
    constexpr int STAGE = (128 + BN) * 128;
    constexpr int WN = BN / 4;
    constexpr int NJ = WN / 8;
    constexpr int BG = WN / 16;
    extern __shared__ char dyn[];
    const uint32_t sbase = s2u(dyn);
    const int tid = threadIdx.x, lane = tid & 31, wid = tid >> 5;
    const int wm = wid >> 2, wn = wid & 3;
    const int m0 = blockIdx.y * 128, n0 = blockIdx.x * BN;
    const int NCtot = TERMS * K / 64;
    const int per = (NCtot + gridDim.z - 1) / gridDim.z;
    const int kc0 = blockIdx.z * per;
    const int kc1 = min(NCtot, kc0 + per);

    float acc[2][NJ][4];
    #pragma unroll
    for (int i = 0; i < 2; i++)
        #pragma unroll
        for (int j = 0; j < NJ; j++)
            #pragma unroll
            for (int k = 0; k < 4; k++) acc[i][j][k] = 0.f;

    auto load_stage = [&](int s, int kc) {
        int kb = kc * 64;
        int seg = (TERMS == 1) ? 0 : kb / K;
        int kk = kb - seg * K;
        const fp16* Asrc = (seg == 1) ? Al : Ah;
        const fp16* Bsrc = (seg == 2) ? Bl : Bh;
        uint32_t st = sbase + s * STAGE;
        #pragma unroll
        for (int j = 0; j < 2; j++) {
            int idx = tid + j * 512;
            int r = idx >> 3, c = idx & 7;
            cpa16(st + r * 128 + ((c ^ (r & 7)) * 16),
                  Asrc + (size_t)(m0 + r) * K + kk + c * 8);
        }
        uint32_t sb = st + 128 * 128;
        #pragma unroll
        for (int j = 0; j < BN / 64; j++) {
            int idx = tid + j * 512;
            int r = idx >> 3, c = idx & 7;
            int nr = n0 + r;
            int ok = nr < Nreal;
            cpa16z(sb + r * 128 + ((c ^ (r & 7)) * 16),
                   Bsrc + (size_t)(ok ? nr : 0) * K + kk + c * 8, ok ? 16 : 0);
        }
    };

    #pragma unroll
    for (int s = 0; s < 3; s++) {
        if (kc0 + s < kc1) load_stage(s, kc0 + s);
        CPA_COMMIT();
    }

    for (int kc = kc0; kc < kc1; kc++) {
        int i = kc - kc0;
        int s = i & 3;
        asm volatile("cp.async.wait_group 2;" ::: "memory");
        __syncthreads();
        if (kc + 3 < kc1) load_stage((i + 3) & 3, kc + 3);
        CPA_COMMIT();

        uint32_t sA = sbase + s * STAGE;
        uint32_t sB = sA + 128 * 128;
        #pragma unroll
        for (int ks = 0; ks < 4; ks++) {
            uint32_t a[2][4], b[BG][4];
            #pragma unroll
            for (int mi = 0; mi < 2; mi++) {
                int r = wm * 32 + mi * 16 + (lane & 15);
                int c = (2 * ks + (lane >> 4)) ^ (r & 7);
                LDSM4(a[mi], sA + r * 128 + c * 16);
            }
            #pragma unroll
            for (int g = 0; g < BG; g++) {
                int r = wn * WN + g * 16 + (lane & 7) + ((lane >> 4) & 1) * 8;
                int c = (2 * ks + ((lane >> 3) & 1)) ^ (r & 7);
                LDSM4(b[g], sB + r * 128 + c * 16);
            }
            #pragma unroll
            for (int mi = 0; mi < 2; mi++)
                #pragma unroll
                for (int nj = 0; nj < NJ; nj++) {
                    int bg = nj >> 1, br = (nj & 1) * 2;
                    MMA16816(acc[mi][nj], a[mi], b[bg][br], b[bg][br+1]);
                }
        }
    }

    #pragma unroll
    for (int mi = 0; mi < 2; mi++)
        #pragma unroll
        for (int nj = 0; nj < NJ; nj++)
            #pragma unroll
            for (int h = 0; h < 2; h++) {
                int m = m0 + wm*32 + mi*16 + (lane >> 2) + h*8;
                int nb = n0 + wn*WN + nj*8 + (lane & 3)*2;
                float vx = acc[mi][nj][h*2], vy = acc[mi][nj][h*2+1];
                size_t ci = (size_t)m * ldc + nb;
                if (EPI == 0) {
                    *(float2*)(o0 + ci) = make_float2(vx, vy);
                } else if (EPI == 1) {
                    vx += e0[nb]; vy += e0[nb+1];
                    float spx = (vx > 20.f) ? vx : log1pf(__expf(vx));
                    float spy = (vy > 20.f) ? vy : log1pf(__expf(vy));
                    float dx = fminf(fmaxf(spx, -10.f), 1.f);
                    float dy = fminf(fmaxf(spy, -10.f), 1.f);
                    float2 ev = *(const float2*)(e1 + ci);
                    *(float2*)(o0 + ci) = make_float2(dx, dy);
                    *(float2*)(o1 + ci) = make_float2(dx * ev.x, dy * ev.y);
                } else if (EPI == 2) {
                    float2 rv = *(const float2*)(e0 + ci);
                    *(float2*)(o0 + ci) = make_float2(vx + rv.x, vy + rv.y);
                } else {
                    if (nb < Nreal) {
                        atomicAdd(o0 + ci, vx);
                        atomicAdd(o0 + ci + 1, vy);
                    }
                }
            }
}

// ---------------- fused weight prep: converts + splits in ONE launch ----------------
// layout: [0, C1) in_proj hi-only | [C1, C2) out_proj hi-only
//         [C2, C3) x_proj hi/lo   | [C3, C4) dt_proj hi/lo
#define C1 (2*D_INNER*D_MODEL/4)
#define C2 (C1 + D_MODEL*D_INNER/4)
#define C3 (C2 + 96*D_INNER/4)
#define C4 (C3 + D_INNER*DT_RANK/4)
__global__ void wprep_kernel(const float4* __restrict__ w_in,
                             const float4* __restrict__ w_op,
                             const float4* __restrict__ w_xp,
                             const float4* __restrict__ w_dt) {
    int i = blockIdx.x * 256 + threadIdx.x;
    if (i >= C4) return;
    const float4* src;
    fp16 *hi, *lo = nullptr;
    int j = i;
    if (i < C1)      { src = w_in; hi = g_inwh; }
    else if (i < C2) { src = w_op; hi = g_opwh; j = i - C1; }
    else if (i < C3) { src = w_xp; hi = g_xpwh; lo = g_xpwl; j = i - C2; }
    else             { src = w_dt; hi = g_dtwh; lo = g_dtwl; j = i - C3; }
    float4 v = src[j];
    fp16 h0 = __float2half(v.x), h1 = __float2half(v.y);
    fp16 h2 = __float2half(v.z), h3 = __float2half(v.w);
    __half2 p0, p1;
    p0.x = h0; p0.y = h1; p1.x = h2; p1.y = h3;
    *(__half2*)(hi + (size_t)j * 4)     = p0;
    *(__half2*)(hi + (size_t)j * 4 + 2) = p1;
    if (lo) {
        __half2 q0, q1;
        q0.x = __float2half(v.x - __half2float(h0));
        q0.y = __float2half(v.y - __half2float(h1));
        q1.x = __float2half(v.z - __half2float(h2));
        q1.y = __float2half(v.w - __half2float(h3));
        *(__half2*)(lo + (size_t)j * 4)     = q0;
        *(__half2*)(lo + (size_t)j * 4 + 2) = q1;
    }
}

__global__ void zero_kernel(float* __restrict__ p, int n) {
    int i = blockIdx.x * 256 + threadIdx.x;
    if (i < n) p[i] = 0.f;
}

__global__ void dtsplit_kernel() {
    int i = blockIdx.x * 256 + threadIdx.x;
    if (i >= MROWS * DT_RANK) return;
    int m = i >> 6, n = i & 63;
    float v = g_xdbc[(size_t)m * 96 + n];
    fp16 h = __float2half(v);
    g_dth[i] = h;
    g_dtl[i] = __float2half(v - __half2float(h));
}

// ---------------- RMSNorm -> fp16 ----------------
__global__ void rmsnorm_kernel(const float* __restrict__ x,
                               const float* __restrict__ w,
                               fp16* __restrict__ oh) {
    int row = blockIdx.x;
    int tid = threadIdx.x;
    const float4* xr = (const float4*)(x + (size_t)row * D_MODEL);
    float4 v = xr[tid];
    float ss = v.x*v.x + v.y*v.y + v.z*v.z + v.w*v.w;
    #pragma unroll
    for (int off = 16; off > 0; off >>= 1)
        ss += __shfl_xor_sync(0xffffffffu, ss, off);
    __shared__ float red[8];
    __shared__ float sscale;
    int lane = tid & 31, wq = tid >> 5;
    if (lane == 0) red[wq] = ss;
    __syncthreads();
    if (tid == 0) {
        float t = 0.f;
        #pragma unroll
        for (int i = 0; i < 8; i++) t += red[i];
        sscale = rsqrtf(t * (1.0f / D_MODEL) + EPSV);
    }
    __syncthreads();
    float sc = sscale;
    float4 wv = ((const float4*)w)[tid];
    float o0 = v.x*sc*wv.x, o1 = v.y*sc*wv.y, o2 = v.z*sc*wv.z, o3 = v.w*sc*wv.w;
    size_t base = (size_t)row * D_MODEL + tid * 4;
    __half2 ph0, ph1;
    ph0.x = __float2half(o0); ph0.y = __float2half(o1);
    ph1.x = __float2half(o2); ph1.y = __float2half(o3);
    *(__half2*)(oh+base)   = ph0; *(__half2*)(oh+base+2) = ph1;
}

// ---------------- depthwise causal conv(4) + silu (+fp16 split) ----------------
__global__ void conv_silu_kernel(const float* __restrict__ cw,
                                 const float* __restrict__ cb) {
    int idx = blockIdx.x * 256 + threadIdx.x;
    if (idx >= MROWS * (D_INNER/4)) return;
    int d4 = idx & (D_INNER/4 - 1);
    int bt = idx >> 9;
    int t  = bt & (TSEQ - 1);
    int d  = d4 * 4;
    float wv[4][4];
    *(float4*)wv[0] = *(const float4*)(cw + (d+0)*4);
    *(float4*)wv[1] = *(const float4*)(cw + (d+1)*4);
    *(float4*)wv[2] = *(const float4*)(cw + (d+2)*4);
    *(float4*)wv[3] = *(const float4*)(cw + (d+3)*4);
    float4 bvv = *(const float4*)(cb + d);
    float a0 = bvv.x, a1 = bvv.y, a2 = bvv.z, a3 = bvv.w;
    #pragma unroll
    for (int k = 0; k < 4; k++) {
        int tt = t - 3 + k;
        if (tt < 0) continue;
        const float4 xv = *(const float4*)(g_xz + (size_t)(bt - t + tt) * (2*D_INNER) + d);
        a0 = fmaf(wv[0][k], xv.x, a0);
        a1 = fmaf(wv[1][k], xv.y, a1);
        a2 = fmaf(wv[2][k], xv.z, a2);
        a3 = fmaf(wv[3][k], xv.w, a3);
    }
    float o0 = a0/(1.f+__expf(-a0)), o1 = a1/(1.f+__expf(-a1));
    float o2 = a2/(1.f+__expf(-a2)), o3 = a3/(1.f+__expf(-a3));
    size_t base = (size_t)bt * D_INNER + d;
    *(float4*)(g_xconv + base) = make_float4(o0,o1,o2,o3);
    fp16 h0=__float2half(o0), h1=__float2half(o1), h2=__float2half(o2), h3=__float2half(o3);
    __half2 ph0, ph1, pl0, pl1;
    ph0.x=h0; ph0.y=h1; ph1.x=h2; ph1.y=h3;
    pl0.x=__float2half(o0-__half2float(h0));
    pl0.y=__float2half(o1-__half2float(h1));
    pl1.x=__float2half(o2-__half2float(h2));
    pl1.y=__float2half(o3-__half2float(h3));
    *(__half2*)(g_xch+base)   = ph0; *(__half2*)(g_xch+base+2) = ph1;
    *(__half2*)(g_xcl+base)   = pl0; *(__half2*)(g_xcl+base+2) = pl1;
}

// ---------------- selective scan (latency-optimized, unchanged except hi-only y) ----------------
__global__ __launch_bounds__(256) void scan_kernel(const float* __restrict__ A_log,
                                                   const float* __restrict__ Dp) {
    __shared__ float sB[64*16], sC[64*16], sdc[64*16], sdu[64*16];
    __shared__ float se[64*16], sg[64*16];
    __shared__ float sP[16*16*17];
    int bid = blockIdx.x;
    int b = bid >> 7;
    int d0 = (bid & 127) << 4;
    int tid = threadIdx.x;
    int w = tid >> 5, lane = tid & 31;
    int s = lane & 15, half = lane >> 4;
    int cl = w * 2 + half;
    int d = d0 + cl;
    int jlo = tid & 15;
    int tl_r = tid >> 4, cl_r = tid & 15;
    float Aval = -__expf(A_log[d * D_STATE + s]);
    float Dvj = Dp[d0 + jlo];
    float h = 0.f;

    for (int t0 = 0; t0 < TSEQ; t0 += 64) {
        for (int i = tid; i < 1024; i += 256) {
            int ti = i >> 4, j = i & 15;
            size_t row = (size_t)b * TSEQ + t0 + ti;
            sB[i]  = g_xdbc[row * 96 + 64 + j];
            sC[i]  = g_xdbc[row * 96 + 80 + j];
            sdc[i] = g_dc[row * D_INNER + d0 + j];
            sdu[i] = g_du[row * D_INNER + d0 + j];
            se[i]  = g_xconv[row * D_INNER + d0 + j] * Dvj;
            float zv = g_xz[row * (2*D_INNER) + D_INNER + d0 + j];
            sg[i]  = zv / (1.f + __expf(-zv));
        }
        __syncthreads();
        #pragma unroll
        for (int sub = 0; sub < 4; sub++) {
            #pragma unroll
            for (int i = 0; i < 16; i++) {
                int t = sub * 16 + i;
                float dcv = sdc[t*16 + cl];
                float duv = sdu[t*16 + cl];
                float r = __expf(dcv * Aval);
                h = fmaf(r, h, duv * sB[t*16 + s]);
                sP[(i*16 + cl)*17 + s] = h * sC[t*16 + s];
            }
            __syncthreads();
            {
                float p = 0.f;
                int base = (tl_r*16 + cl_r)*17;
                #pragma unroll
                for (int q = 0; q < 16; q++) p += sP[base + q];
                int t = sub * 16 + tl_r;
                float yv = (p + se[t*16 + cl_r]) * sg[t*16 + cl_r];
                size_t row = (size_t)b * TSEQ + t0 + t;
                g_yh[row * D_INNER + d0 + cl_r] = __float2half(yv);
            }
            __syncthreads();
        }
    }
}

// ---------------- launch ----------------
#define SM256 ((128 + 256) * 128 * 4)   /* 196608 */
#define SM128 ((128 + 128) * 128 * 4)   /* 131072 */

extern "C" void kernel_launch(void* const* d_in, const int* in_sizes, int n_in,
                              void* d_out, int out_size) {
    (void)in_sizes; (void)n_in; (void)out_size;
    const float* x          = (const float*)d_in[0];
    const float* in_proj_w  = (const float*)d_in[1];
    const float* conv_w     = (const float*)d_in[2];
    const float* conv_b     = (const float*)d_in[3];
    const float* x_proj_w   = (const float*)d_in[4];
    const float* dt_proj_w  = (const float*)d_in[5];
    const float* dt_proj_b  = (const float*)d_in[6];
    const float* A_log      = (const float*)d_in[7];
    const float* Dp         = (const float*)d_in[8];
    const float* out_proj_w = (const float*)d_in[9];
    const float* norm_w     = (const float*)d_in[10];
    float* out = (float*)d_out;

    fp16 *xnh, *inwh, *xpwh, *xpwl, *dtwh, *dtwl, *opwh;
    fp16 *xch, *xcl, *dth, *dtl, *yh;
    float *xz, *xconv, *xdbc, *dcb, *dub;
    cudaGetSymbolAddress((void**)&xnh,  g_xnh);
    cudaGetSymbolAddress((void**)&inwh, g_inwh);
    cudaGetSymbolAddress((void**)&xpwh, g_xpwh); cudaGetSymbolAddress((void**)&xpwl, g_xpwl);
    cudaGetSymbolAddress((void**)&dtwh, g_dtwh); cudaGetSymbolAddress((void**)&dtwl, g_dtwl);
    cudaGetSymbolAddress((void**)&opwh, g_opwh);
    cudaGetSymbolAddress((void**)&xch,  g_xch);  cudaGetSymbolAddress((void**)&xcl,  g_xcl);
    cudaGetSymbolAddress((void**)&dth,  g_dth);  cudaGetSymbolAddress((void**)&dtl,  g_dtl);
    cudaGetSymbolAddress((void**)&yh,   g_yh);
    cudaGetSymbolAddress((void**)&xz,    g_xz);
    cudaGetSymbolAddress((void**)&xconv, g_xconv);
    cudaGetSymbolAddress((void**)&xdbc,  g_xdbc);
    cudaGetSymbolAddress((void**)&dcb,   g_dc);
    cudaGetSymbolAddress((void**)&dub,   g_du);

    cudaFuncSetAttribute((const void*)gemm_mma<0,256,1>, cudaFuncAttributeMaxDynamicSharedMemorySize, SM256);
    cudaFuncSetAttribute((const void*)gemm_mma<1,256,3>, cudaFuncAttributeMaxDynamicSharedMemorySize, SM256);
    cudaFuncSetAttribute((const void*)gemm_mma<2,256,1>, cudaFuncAttributeMaxDynamicSharedMemorySize, SM256);
    cudaFuncSetAttribute((const void*)gemm_mma<4,128,3>, cudaFuncAttributeMaxDynamicSharedMemorySize, SM128);

    // fused weight prep + xdbc zero
    wprep_kernel<<<(C4 + 255)/256, 256>>>((const float4*)in_proj_w, (const float4*)out_proj_w,
                                          (const float4*)x_proj_w,  (const float4*)dt_proj_w);
    zero_kernel<<<(MROWS*96 + 255)/256, 256>>>(xdbc, MROWS*96);

    // 1. rmsnorm -> fp16
    rmsnorm_kernel<<<MROWS, 256>>>(x, norm_w, xnh);

    // 2. in_proj (1-term fp16)
    gemm_mma<0,256,1><<<dim3(16, 32, 1), 512, SM256>>>(xnh, xnh, inwh, inwh,
        D_MODEL, 2*D_INNER, 2*D_INNER, xz, nullptr, nullptr, nullptr);

    // 3. conv + silu (+split for 3-term x_proj)
    conv_silu_kernel<<<(MROWS * (D_INNER/4) + 255)/256, 256>>>(conv_w, conv_b);

    // 4. x_proj (3-term, split-K=4)
    gemm_mma<4,128,3><<<dim3(1, 32, 4), 512, SM128>>>(xch, xcl, xpwh, xpwl,
        D_INNER, 96, 96, xdbc, nullptr, nullptr, nullptr);

    // 4b. dt hi/lo split
    dtsplit_kernel<<<(MROWS*DT_RANK + 255)/256, 256>>>();

    // 5. dt_proj (3-term) + softplus/clip/du epilogue
    gemm_mma<1,256,3><<<dim3(8, 32, 1), 512, SM256>>>(dth, dtl, dtwh, dtwl,
        DT_RANK, D_INNER, D_INNER, dcb, dub, dt_proj_b, xconv);

    // 6. selective scan
    scan_kernel<<<NB * (D_INNER/16), 256>>>(A_log, Dp);

    // 7. out_proj (1-term fp16) + residual
    gemm_mma<2,256,1><<<dim3(4, 32, 1), 512, SM256>>>(yh, yh, opwh, opwh,
        D_INNER, D_MODEL, D_MODEL, out, nullptr, x, nullptr);
}

// round 8
// speedup vs baseline: 6.5211x; 1.0528x over previous
#include <cuda_runtime.h>
#include <cuda_fp16.h>
#include <math.h>
#include <stdint.h>

#define D_MODEL 1024
#define D_INNER 2048
#define D_STATE 16
#define DT_RANK 64
#define NB 2
#define TSEQ 2048
#define MROWS (NB*TSEQ)   /* 4096 */
#define EPSV 1e-6f

typedef __half fp16;

// ---------------- scratch (no allocations allowed) ----------------
__device__ fp16  g_xnh[MROWS*D_MODEL];
__device__ fp16  g_inwh[2*D_INNER*D_MODEL];
__device__ fp16  g_xpwh[96*D_INNER],    g_xpwl[96*D_INNER];
__device__ fp16  g_dtwh[D_INNER*DT_RANK], g_dtwl[D_INNER*DT_RANK];
__device__ fp16  g_opwh[D_MODEL*D_INNER];
__device__ float g_xz[MROWS*2*D_INNER];
__device__ float g_xconv[MROWS*D_INNER];
__device__ fp16  g_xch[MROWS*D_INNER],  g_xcl[MROWS*D_INNER];
__device__ float g_xdbc[MROWS*96];
__device__ fp16  g_dth[MROWS*DT_RANK],  g_dtl[MROWS*DT_RANK];
__device__ float g_dc[MROWS*D_INNER],   g_du[MROWS*D_INNER];
__device__ fp16  g_yh[MROWS*D_INNER];

// ---------------- helpers ----------------
__device__ __forceinline__ uint32_t s2u(const void* p) {
    uint32_t a;
    asm("{ .reg .u64 t; cvta.to.shared.u64 t, %1; cvt.u32.u64 %0, t; }" : "=r"(a) : "l"(p));
    return a;
}
__device__ __forceinline__ void cpa16(uint32_t dst, const void* src) {
    asm volatile("cp.async.cg.shared.global [%0], [%1], 16;" :: "r"(dst), "l"(src) : "memory");
}
__device__ __forceinline__ void cpa16z(uint32_t dst, const void* src, int sz) {
    asm volatile("cp.async.cg.shared.global [%0], [%1], 16, %2;" :: "r"(dst), "l"(src), "r"(sz) : "memory");
}
#define CPA_COMMIT() asm volatile("cp.async.commit_group;" ::: "memory")

#define LDSM4(r, a) \
    asm volatile("ldmatrix.sync.aligned.m8n8.x4.shared.b16 {%0,%1,%2,%3}, [%4];" \
        : "=r"((r)[0]),"=r"((r)[1]),"=r"((r)[2]),"=r"((r)[3]) : "r"(a))

#define MMA16816(d, a, b0, b1) \
    asm volatile("mma.sync.aligned.m16n8k16.row.col.f32.f16.f16.f32 " \
        "{%0,%1,%2,%3}, {%4,%5,%6,%7}, {%8,%9}, {%0,%1,%2,%3};" \
        : "+f"((d)[0]),"+f"((d)[1]),"+f"((d)[2]),"+f"((d)[3]) \
        : "r"((a)[0]),"r"((a)[1]),"r"((a)[2]),"r"((a)[3]), "r"(b0),"r"(b1))

// ---------------- split-fp16 GEMM via mma.sync ----------------
// 128x128 tile, BK=64, 3-stage cp.async ring (96KB) -> 2 CTAs/SM.
// 256 threads = 8 warps (2x4); warp tile 64x32.
// TERMS=1: Ah*Bh     TERMS=3: Ah*Bh, Al*Bh, Ah*Bl
// EPI 0: C=v   EPI 1: dt epi   EPI 2: C=v+res   EPI 4: atomicAdd (split-K)
#define GSMEM (3 * 32768)
template<int EPI, int TERMS>
__global__ __launch_bounds__(256, 2)
void gemm_mma(const fp16* __restrict__ Ah, const fp16* __restrict__ Al,
              const fp16* __restrict__ Bh, const fp16* __restrict__ Bl,
              int K, int Nreal, int ldc,
              float* __restrict__ o0, float* __restrict__ o1,
              const float* __restrict__ e0, const float* __restrict__ e1)
{
    extern __shared__ char dyn[];
    const uint32_t sbase = s2u(dyn);
    const int tid = threadIdx.x, lane = tid & 31, wid = tid >> 5;
    const int wm = wid >> 2, wn = wid & 3;    // 2 x 4 warp grid
    const int m0 = blockIdx.y * 128, n0 = blockIdx.x * 128;
    const int NCtot = TERMS * K / 64;
    const int per = (NCtot + gridDim.z - 1) / gridDim.z;
    const int kc0 = blockIdx.z * per;
    const int kc1 = min(NCtot, kc0 + per);

    float acc[4][4][4];
    #pragma unroll
    for (int i = 0; i < 4; i++)
        #pragma unroll
        for (int j = 0; j < 4; j++)
            #pragma unroll
            for (int k = 0; k < 4; k++) acc[i][j][k] = 0.f;

    auto load_stage = [&](int s, int kc) {
        int kb = kc * 64;
        int seg = (TERMS == 1) ? 0 : kb / K;
        int kk = kb - seg * K;
        const fp16* Asrc = (seg == 1) ? Al : Ah;
        const fp16* Bsrc = (seg == 2) ? Bl : Bh;
        uint32_t st = sbase + s * 32768;
        #pragma unroll
        for (int j = 0; j < 4; j++) {                 // A: 1024 16B chunks
            int idx = tid + j * 256;
            int r = idx >> 3, c = idx & 7;
            cpa16(st + r * 128 + ((c ^ (r & 7)) * 16),
                  Asrc + (size_t)(m0 + r) * K + kk + c * 8);
        }
        uint32_t sb = st + 16384;
        #pragma unroll
        for (int j = 0; j < 4; j++) {                 // B: 1024 chunks
            int idx = tid + j * 256;
            int r = idx >> 3, c = idx & 7;
            int nr = n0 + r;
            int ok = nr < Nreal;
            cpa16z(sb + r * 128 + ((c ^ (r & 7)) * 16),
                   Bsrc + (size_t)(ok ? nr : 0) * K + kk + c * 8, ok ? 16 : 0);
        }
    };

    if (kc0 < kc1)     load_stage(0, kc0);
    CPA_COMMIT();
    if (kc0 + 1 < kc1) load_stage(1, kc0 + 1);
    CPA_COMMIT();

    for (int kc = kc0; kc < kc1; kc++) {
        int i = kc - kc0;
        int s = i % 3;
        asm volatile("cp.async.wait_group 1;" ::: "memory");
        __syncthreads();
        if (kc + 2 < kc1) load_stage((i + 2) % 3, kc + 2);
        CPA_COMMIT();

        uint32_t sA = sbase + s * 32768;
        uint32_t sB = sA + 16384;
        #pragma unroll
        for (int ks = 0; ks < 4; ks++) {
            uint32_t a[4][4], b[2][4];
            #pragma unroll
            for (int mi = 0; mi < 4; mi++) {
                int r = wm * 64 + mi * 16 + (lane & 15);
                int c = (2 * ks + (lane >> 4)) ^ (r & 7);
                LDSM4(a[mi], sA + r * 128 + c * 16);
            }
            #pragma unroll
            for (int g = 0; g < 2; g++) {
                int r = wn * 32 + g * 16 + (lane & 7) + ((lane >> 4) & 1) * 8;
                int c = (2 * ks + ((lane >> 3) & 1)) ^ (r & 7);
                LDSM4(b[g], sB + r * 128 + c * 16);
            }
            #pragma unroll
            for (int mi = 0; mi < 4; mi++)
                #pragma unroll
                for (int nj = 0; nj < 4; nj++) {
                    int bg = nj >> 1, br = (nj & 1) * 2;
                    MMA16816(acc[mi][nj], a[mi], b[bg][br], b[bg][br+1]);
                }
        }
    }

    // ---- epilogue straight from registers (float2 pairs) ----
    #pragma unroll
    for (int mi = 0; mi < 4; mi++)
        #pragma unroll
        for (int nj = 0; nj < 4; nj++)
            #pragma unroll
            for (int h = 0; h < 2; h++) {
                int m = m0 + wm*64 + mi*16 + (lane >> 2) + h*8;
                int nb = n0 + wn*32 + nj*8 + (lane & 3)*2;
                float vx = acc[mi][nj][h*2], vy = acc[mi][nj][h*2+1];
                size_t ci = (size_t)m * ldc + nb;
                if (EPI == 0) {
                    *(float2*)(o0 + ci) = make_float2(vx, vy);
                } else if (EPI == 1) {
                    vx += e0[nb]; vy += e0[nb+1];
                    float spx = (vx > 20.f) ? vx : log1pf(__expf(vx));
                    float spy = (vy > 20.f) ? vy : log1pf(__expf(vy));
                    float dx = fminf(fmaxf(spx, -10.f), 1.f);
                    float dy = fminf(fmaxf(spy, -10.f), 1.f);
                    float2 ev = *(const float2*)(e1 + ci);
                    *(float2*)(o0 + ci) = make_float2(dx, dy);
                    *(float2*)(o1 + ci) = make_float2(dx * ev.x, dy * ev.y);
                } else if (EPI == 2) {
                    float2 rv = *(const float2*)(e0 + ci);
                    *(float2*)(o0 + ci) = make_float2(vx + rv.x, vy + rv.y);
                } else {
                    if (nb < Nreal) {
                        atomicAdd(o0 + ci, vx);
                        atomicAdd(o0 + ci + 1, vy);
                    }
                }
            }
}

// ---------------- fused weight prep ----------------
#define C1 (2*D_INNER*D_MODEL/4)
#define C2 (C1 + D_MODEL*D_INNER/4)
#define C3 (C2 + 96*D_INNER/4)
#define C4 (C3 + D_INNER*DT_RANK/4)
__global__ void wprep_kernel(const float4* __restrict__ w_in,
                             const float4* __restrict__ w_op,
                             const float4* __restrict__ w_xp,
                             const float4* __restrict__ w_dt) {
    int i = blockIdx.x * 256 + threadIdx.x;
    if (i >= C4) return;
    const float4* src;
    fp16 *hi, *lo = nullptr;
    int j = i;
    if (i < C1)      { src = w_in; hi = g_inwh; }
    else if (i < C2) { src = w_op; hi = g_opwh; j = i - C1; }
    else if (i < C3) { src = w_xp; hi = g_xpwh; lo = g_xpwl; j = i - C2; }
    else             { src = w_dt; hi = g_dtwh; lo = g_dtwl; j = i - C3; }
    float4 v = src[j];
    fp16 h0 = __float2half(v.x), h1 = __float2half(v.y);
    fp16 h2 = __float2half(v.z), h3 = __float2half(v.w);
    __half2 p0, p1;
    p0.x = h0; p0.y = h1; p1.x = h2; p1.y = h3;
    *(__half2*)(hi + (size_t)j * 4)     = p0;
    *(__half2*)(hi + (size_t)j * 4 + 2) = p1;
    if (lo) {
        __half2 q0, q1;
        q0.x = __float2half(v.x - __half2float(h0));
        q0.y = __float2half(v.y - __half2float(h1));
        q1.x = __float2half(v.z - __half2float(h2));
        q1.y = __float2half(v.w - __half2float(h3));
        *(__half2*)(lo + (size_t)j * 4)     = q0;
        *(__half2*)(lo + (size_t)j * 4 + 2) = q1;
    }
}

__global__ void zero_kernel(float* __restrict__ p, int n) {
    int i = blockIdx.x * 256 + threadIdx.x;
    if (i < n) p[i] = 0.f;
}

__global__ void dtsplit_kernel() {
    int i = blockIdx.x * 256 + threadIdx.x;
    if (i >= MROWS * DT_RANK) return;
    int m = i >> 6, n = i & 63;
    float v = g_xdbc[(size_t)m * 96 + n];
    fp16 h = __float2half(v);
    g_dth[i] = h;
    g_dtl[i] = __float2half(v - __half2float(h));
}

// ---------------- RMSNorm -> fp16 ----------------
__global__ void rmsnorm_kernel(const float* __restrict__ x,
                               const float* __restrict__ w,
                               fp16* __restrict__ oh) {
    int row = blockIdx.x;
    int tid = threadIdx.x;
    const float4* xr = (const float4*)(x + (size_t)row * D_MODEL);
    float4 v = xr[tid];
    float ss = v.x*v.x + v.y*v.y + v.z*v.z + v.w*v.w;
    #pragma unroll
    for (int off = 16; off > 0; off >>= 1)
        ss += __shfl_xor_sync(0xffffffffu, ss, off);
    __shared__ float red[8];
    __shared__ float sscale;
    int lane = tid & 31, wq = tid >> 5;
    if (lane == 0) red[wq] = ss;
    __syncthreads();
    if (tid == 0) {
        float t = 0.f;
        #pragma unroll
        for (int i = 0; i < 8; i++) t += red[i];
        sscale = rsqrtf(t * (1.0f / D_MODEL) + EPSV);
    }
    __syncthreads();
    float sc = sscale;
    float4 wv = ((const float4*)w)[tid];
    float o0 = v.x*sc*wv.x, o1 = v.y*sc*wv.y, o2 = v.z*sc*wv.z, o3 = v.w*sc*wv.w;
    size_t base = (size_t)row * D_MODEL + tid * 4;
    __half2 ph0, ph1;
    ph0.x = __float2half(o0); ph0.y = __float2half(o1);
    ph1.x = __float2half(o2); ph1.y = __float2half(o3);
    *(__half2*)(oh+base)   = ph0; *(__half2*)(oh+base+2) = ph1;
}

// ---------------- depthwise causal conv(4) + silu (+fp16 split) ----------------
__global__ void conv_silu_kernel(const float* __restrict__ cw,
                                 const float* __restrict__ cb) {
    int idx = blockIdx.x * 256 + threadIdx.x;
    if (idx >= MROWS * (D_INNER/4)) return;
    int d4 = idx & (D_INNER/4 - 1);
    int bt = idx >> 9;
    int t  = bt & (TSEQ - 1);
    int d  = d4 * 4;
    float wv[4][4];
    *(float4*)wv[0] = *(const float4*)(cw + (d+0)*4);
    *(float4*)wv[1] = *(const float4*)(cw + (d+1)*4);
    *(float4*)wv[2] = *(const float4*)(cw + (d+2)*4);
    *(float4*)wv[3] = *(const float4*)(cw + (d+3)*4);
    float4 bvv = *(const float4*)(cb + d);
    float a0 = bvv.x, a1 = bvv.y, a2 = bvv.z, a3 = bvv.w;
    #pragma unroll
    for (int k = 0; k < 4; k++) {
        int tt = t - 3 + k;
        if (tt < 0) continue;
        const float4 xv = *(const float4*)(g_xz + (size_t)(bt - t + tt) * (2*D_INNER) + d);
        a0 = fmaf(wv[0][k], xv.x, a0);
        a1 = fmaf(wv[1][k], xv.y, a1);
        a2 = fmaf(wv[2][k], xv.z, a2);
        a3 = fmaf(wv[3][k], xv.w, a3);
    }
    float o0 = a0/(1.f+__expf(-a0)), o1 = a1/(1.f+__expf(-a1));
    float o2 = a2/(1.f+__expf(-a2)), o3 = a3/(1.f+__expf(-a3));
    size_t base = (size_t)bt * D_INNER + d;
    *(float4*)(g_xconv + base) = make_float4(o0,o1,o2,o3);
    fp16 h0=__float2half(o0), h1=__float2half(o1), h2=__float2half(o2), h3=__float2half(o3);
    __half2 ph0, ph1, pl0, pl1;
    ph0.x=h0; ph0.y=h1; ph1.x=h2; ph1.y=h3;
    pl0.x=__float2half(o0-__half2float(h0));
    pl0.y=__float2half(o1-__half2float(h1));
    pl1.x=__float2half(o2-__half2float(h2));
    pl1.y=__float2half(o3-__half2float(h3));
    *(__half2*)(g_xch+base)   = ph0; *(__half2*)(g_xch+base+2) = ph1;
    *(__half2*)(g_xcl+base)   = pl0; *(__half2*)(g_xcl+base+2) = pl1;
}

// ---------------- selective scan (latency-optimized) ----------------
__global__ __launch_bounds__(256) void scan_kernel(const float* __restrict__ A_log,
                                                   const float* __restrict__ Dp) {
    __shared__ float sB[64*16], sC[64*16], sdc[64*16], sdu[64*16];
    __shared__ float se[64*16], sg[64*16];
    __shared__ float sP[16*16*17];
    int bid = blockIdx.x;
    int b = bid >> 7;
    int d0 = (bid & 127) << 4;
    int tid = threadIdx.x;
    int w = tid >> 5, lane = tid & 31;
    int s = lane & 15, half = lane >> 4;
    int cl = w * 2 + half;
    int d = d0 + cl;
    int jlo = tid & 15;
    int tl_r = tid >> 4, cl_r = tid & 15;
    float Aval = -__expf(A_log[d * D_STATE + s]);
    float Dvj = Dp[d0 + jlo];
    float h = 0.f;

    for (int t0 = 0; t0 < TSEQ; t0 += 64) {
        for (int i = tid; i < 1024; i += 256) {
            int ti = i >> 4, j = i & 15;
            size_t row = (size_t)b * TSEQ + t0 + ti;
            sB[i]  = g_xdbc[row * 96 + 64 + j];
            sC[i]  = g_xdbc[row * 96 + 80 + j];
            sdc[i] = g_dc[row * D_INNER + d0 + j];
            sdu[i] = g_du[row * D_INNER + d0 + j];
            se[i]  = g_xconv[row * D_INNER + d0 + j] * Dvj;
            float zv = g_xz[row * (2*D_INNER) + D_INNER + d0 + j];
            sg[i]  = zv / (1.f + __expf(-zv));
        }
        __syncthreads();
        #pragma unroll
        for (int sub = 0; sub < 4; sub++) {
            #pragma unroll
            for (int i = 0; i < 16; i++) {
                int t = sub * 16 + i;
                float dcv = sdc[t*16 + cl];
                float duv = sdu[t*16 + cl];
                float r = __expf(dcv * Aval);
                h = fmaf(r, h, duv * sB[t*16 + s]);
                sP[(i*16 + cl)*17 + s] = h * sC[t*16 + s];
            }
            __syncthreads();
            {
                float p = 0.f;
                int base = (tl_r*16 + cl_r)*17;
                #pragma unroll
                for (int q = 0; q < 16; q++) p += sP[base + q];
                int t = sub * 16 + tl_r;
                float yv = (p + se[t*16 + cl_r]) * sg[t*16 + cl_r];
                size_t row = (size_t)b * TSEQ + t0 + t;
                g_yh[row * D_INNER + d0 + cl_r] = __float2half(yv);
            }
            __syncthreads();
        }
    }
}

// ---------------- launch ----------------
extern "C" void kernel_launch(void* const* d_in, const int* in_sizes, int n_in,
                              void* d_out, int out_size) {
    (void)in_sizes; (void)n_in; (void)out_size;
    const float* x          = (const float*)d_in[0];
    const float* in_proj_w  = (const float*)d_in[1];
    const float* conv_w     = (const float*)d_in[2];
    const float* conv_b     = (const float*)d_in[3];
    const float* x_proj_w   = (const float*)d_in[4];
    const float* dt_proj_w  = (const float*)d_in[5];
    const float* dt_proj_b  = (const float*)d_in[6];
    const float* A_log      = (const float*)d_in[7];
    const float* Dp         = (const float*)d_in[8];
    const float* out_proj_w = (const float*)d_in[9];
    const float* norm_w     = (const float*)d_in[10];
    float* out = (float*)d_out;

    fp16 *xnh, *inwh, *xpwh, *xpwl, *dtwh, *dtwl, *opwh;
    fp16 *xch, *xcl, *dth, *dtl, *yh;
    float *xz, *xconv, *xdbc, *dcb, *dub;
    cudaGetSymbolAddress((void**)&xnh,  g_xnh);
    cudaGetSymbolAddress((void**)&inwh, g_inwh);
    cudaGetSymbolAddress((void**)&xpwh, g_xpwh); cudaGetSymbolAddress((void**)&xpwl, g_xpwl);
    cudaGetSymbolAddress((void**)&dtwh, g_dtwh); cudaGetSymbolAddress((void**)&dtwl, g_dtwl);
    cudaGetSymbolAddress((void**)&opwh, g_opwh);
    cudaGetSymbolAddress((void**)&xch,  g_xch);  cudaGetSymbolAddress((void**)&xcl,  g_xcl);
    cudaGetSymbolAddress((void**)&dth,  g_dth);  cudaGetSymbolAddress((void**)&dtl,  g_dtl);
    cudaGetSymbolAddress((void**)&yh,   g_yh);
    cudaGetSymbolAddress((void**)&xz,    g_xz);
    cudaGetSymbolAddress((void**)&xconv, g_xconv);
    cudaGetSymbolAddress((void**)&xdbc,  g_xdbc);
    cudaGetSymbolAddress((void**)&dcb,   g_dc);
    cudaGetSymbolAddress((void**)&dub,   g_du);

    cudaFuncSetAttribute((const void*)gemm_mma<0,1>, cudaFuncAttributeMaxDynamicSharedMemorySize, GSMEM);
    cudaFuncSetAttribute((const void*)gemm_mma<1,3>, cudaFuncAttributeMaxDynamicSharedMemorySize, GSMEM);
    cudaFuncSetAttribute((const void*)gemm_mma<2,1>, cudaFuncAttributeMaxDynamicSharedMemorySize, GSMEM);
    cudaFuncSetAttribute((const void*)gemm_mma<4,3>, cudaFuncAttributeMaxDynamicSharedMemorySize, GSMEM);

    // fused weight prep + xdbc zero
    wprep_kernel<<<(C4 + 255)/256, 256>>>((const float4*)in_proj_w, (const float4*)out_proj_w,
                                          (const float4*)x_proj_w,  (const float4*)dt_proj_w);
    zero_kernel<<<(MROWS*96 + 255)/256, 256>>>(xdbc, MROWS*96);

    // 1. rmsnorm -> fp16
    rmsnorm_kernel<<<MROWS, 256>>>(x, norm_w, xnh);

    // 2. in_proj (1-term fp16)
    gemm_mma<0,1><<<dim3(32, 32, 1), 256, GSMEM>>>(xnh, xnh, inwh, inwh,
        D_MODEL, 2*D_INNER, 2*D_INNER, xz, nullptr, nullptr, nullptr);

    // 3. conv + silu (+split for 3-term x_proj)
    conv_silu_kernel<<<(MROWS * (D_INNER/4) + 255)/256, 256>>>(conv_w, conv_b);

    // 4. x_proj (3-term, split-K=8)
    gemm_mma<4,3><<<dim3(1, 32, 8), 256, GSMEM>>>(xch, xcl, xpwh, xpwl,
        D_INNER, 96, 96, xdbc, nullptr, nullptr, nullptr);

    // 4b. dt hi/lo split
    dtsplit_kernel<<<(MROWS*DT_RANK + 255)/256, 256>>>();

    // 5. dt_proj (3-term) + softplus/clip/du epilogue
    gemm_mma<1,3><<<dim3(16, 32, 1), 256, GSMEM>>>(dth, dtl, dtwh, dtwl,
        DT_RANK, D_INNER, D_INNER, dcb, dub, dt_proj_b, xconv);

    // 6. selective scan
    scan_kernel<<<NB * (D_INNER/16), 256>>>(A_log, Dp);

    // 7. out_proj (1-term fp16) + residual
    gemm_mma<2,1><<<dim3(8, 32, 1), 256, GSMEM>>>(yh, yh, opwh, opwh,
        D_INNER, D_MODEL, D_MODEL, out, nullptr, x, nullptr);
}